// round 12
// baseline (speedup 1.0000x reference)
#include <cuda_runtime.h>
#include <cuda_bf16.h>
#include <cstdint>

#define N_   16
#define C_   384
#define S_   1024
#define NH_  6
#define D_   64
#define C3_  1152
#define M_   (N_*S_)

typedef __nv_bfloat16 bf16;

__device__ bf16 g_tok_hi[M_*C_],  g_tok_lo[M_*C_];
__device__ bf16 g_wqkv_hi[C3_*C_], g_wqkv_lo[C3_*C_];
__device__ bf16 g_wout_hi[C_*C_],  g_wout_lo[C_*C_];
__device__ float g_q[N_*NH_*S_*D_];                    // fp32, 0.125 folded
__device__ bf16 g_kh[N_*NH_*S_*D_], g_kl[N_*NH_*S_*D_];
__device__ bf16 g_vh[N_*NH_*D_*S_], g_vl[N_*NH_*D_*S_];   // V^T [nh][d][s]
__device__ bf16 g_ao_hi[M_*C_], g_ao_lo[M_*C_];

__device__ __forceinline__ uint32_t smem_u32(const void* p) {
    uint32_t a;
    asm("{ .reg .u64 t; cvta.to.shared.u64 t, %1; cvt.u32.u64 %0, t; }" : "=r"(a) : "l"(p));
    return a;
}
__device__ __forceinline__ void ldsm4(uint32_t a, uint32_t& r0, uint32_t& r1,
                                      uint32_t& r2, uint32_t& r3) {
    asm volatile("ldmatrix.sync.aligned.m8n8.x4.shared.b16 {%0,%1,%2,%3}, [%4];"
        : "=r"(r0), "=r"(r1), "=r"(r2), "=r"(r3) : "r"(a));
}
__device__ __forceinline__ void cp16(uint32_t saddr, const void* g) {
    size_t ga = __cvta_generic_to_global(g);
    asm volatile("cp.async.cg.shared.global [%0], [%1], 16;" :: "r"(saddr), "l"(ga) : "memory");
}
#define CP_COMMIT() asm volatile("cp.async.commit_group;" ::: "memory")
#define CP_WAIT0()  asm volatile("cp.async.wait_group 0;" ::: "memory")
#define CP_WAIT1()  asm volatile("cp.async.wait_group 1;" ::: "memory")
#define CP_WAIT2()  asm volatile("cp.async.wait_group 2;" ::: "memory")

__device__ __forceinline__ uint32_t bfpair(float a, float b) {
    __nv_bfloat162 t; t.x = __float2bfloat16(a); t.y = __float2bfloat16(b);
    return *(uint32_t*)&t;
}
__device__ __forceinline__ void bfsplit2(float a, float b, uint32_t& h, uint32_t& l) {
    bf16 ha = __float2bfloat16(a), hb = __float2bfloat16(b);
    __nv_bfloat162 hp; hp.x = ha; hp.y = hb;
    h = *(uint32_t*)&hp;
    l = bfpair(a - __bfloat162float(ha), b - __bfloat162float(hb));
}

#define MMA_BF16(d, a, b0, b1)                                                \
    asm volatile("mma.sync.aligned.m16n8k16.row.col.f32.bf16.bf16.f32 "       \
        "{%0,%1,%2,%3}, {%4,%5,%6,%7}, {%8,%9}, {%0,%1,%2,%3};"               \
        : "+f"((d)[0]), "+f"((d)[1]), "+f"((d)[2]), "+f"((d)[3])              \
        : "r"((a)[0]), "r"((a)[1]), "r"((a)[2]), "r"((a)[3]),                 \
          "r"(b0), "r"(b1))

// ---------------- input prep ----------------
__global__ void transpose_x(const float* __restrict__ x) {
    __shared__ float t[32][33];
    int n = blockIdx.z, k0 = blockIdx.y * 32, s0 = blockIdx.x * 32;
    int tx = threadIdx.x, ty = threadIdx.y;
    const float* src = x + ((size_t)n * C_ + k0) * S_ + s0;
    #pragma unroll
    for (int j = 0; j < 4; j++)
        t[ty + 8 * j][tx] = src[(size_t)(ty + 8 * j) * S_ + tx];
    __syncthreads();
    size_t base = ((size_t)n * S_ + s0) * C_ + k0;
    #pragma unroll
    for (int j = 0; j < 4; j++) {
        float a = t[tx][ty + 8 * j];
        bf16 h = __float2bfloat16(a);
        size_t o = base + (size_t)(ty + 8 * j) * C_ + tx;
        g_tok_hi[o] = h;
        g_tok_lo[o] = __float2bfloat16(a - __bfloat162float(h));
    }
}
__global__ void split_wqkv(const float* __restrict__ w) {
    int i = blockIdx.x * 256 + threadIdx.x;
    if (i < C3_ * C_) {
        float a = w[i]; bf16 h = __float2bfloat16(a);
        g_wqkv_hi[i] = h; g_wqkv_lo[i] = __float2bfloat16(a - __bfloat162float(h));
    }
}
__global__ void split_wout(const float* __restrict__ w) {
    int i = blockIdx.x * 256 + threadIdx.x;
    if (i < C_ * C_) {
        float a = w[i]; bf16 h = __float2bfloat16(a);
        g_wout_hi[i] = h; g_wout_lo[i] = __float2bfloat16(a - __bfloat162float(h));
    }
}

// ---------------- 3xBF16 mma.sync GEMM (2-stage, KCH=32, ldmatrix) --------
#define KCH 32
#define HALF_B (128*80)
#define STAGE_B (4*HALF_B)
#define GEMM_SMEM (2*STAGE_B)

__global__ __launch_bounds__(256) void mma_gemm(
    int mode, const float* __restrict__ bias, float* __restrict__ out)
{
    extern __shared__ __align__(16) char smem[];
    uint32_t sbase = smem_u32(smem);
    int tid = threadIdx.x;
    int lane = tid & 31, w = tid >> 5;
    int wm = w & 3, wn = w >> 2;
    int by = blockIdx.y, bx = blockIdx.x;
    int rq = lane >> 2, kq = lane & 3;
    int l15 = lane & 15, lhi = lane >> 4;     // A ldsm addressing
    int g8 = lane >> 3, l7 = lane & 7;        // B ldsm addressing

    const bf16 *Ahp, *Alp, *Bhp, *Blp;
    if (mode == 0) { Ahp = g_tok_hi;  Alp = g_tok_lo;  Bhp = g_wqkv_hi; Blp = g_wqkv_lo; }
    else           { Ahp = g_wout_hi; Alp = g_wout_lo; Bhp = g_ao_hi;   Blp = g_ao_lo; }
    const bf16* Ah = Ahp + (size_t)by * 128 * C_;
    const bf16* Al = Alp + (size_t)by * 128 * C_;
    const bf16* Bh = Bhp + (size_t)bx * 128 * C_;
    const bf16* Bl = Blp + (size_t)bx * 128 * C_;

    float acc[2][8][4];
    #pragma unroll
    for (int i = 0; i < 2; i++)
        #pragma unroll
        for (int j = 0; j < 8; j++)
            #pragma unroll
            for (int q = 0; q < 4; q++) acc[i][j][q] = 0.0f;

    auto issue = [&](int c, int st) {
        uint32_t s0 = sbase + st * STAGE_B;
        #pragma unroll
        for (int i = 0; i < 2; i++) {
            int idx = i * 256 + tid;
            int row = idx >> 2, seg = idx & 3;
            size_t go = (size_t)row * C_ + c * KCH + seg * 8;
            uint32_t so = row * 80 + seg * 16;
            cp16(s0 + so,              Ah + go);
            cp16(s0 + HALF_B + so,     Al + go);
            cp16(s0 + 2 * HALF_B + so, Bh + go);
            cp16(s0 + 3 * HALF_B + so, Bl + go);
        }
        CP_COMMIT();
    };

    const int NCH = C_ / KCH;   // 12
    issue(0, 0);
    for (int c = 0; c < NCH; c++) {
        int st = c & 1;
        if (c + 1 < NCH) { issue(c + 1, st ^ 1); CP_WAIT1(); }
        else             { CP_WAIT0(); }
        __syncthreads();

        uint32_t sA  = sbase + st * STAGE_B;
        uint32_t sAl = sA + HALF_B;
        uint32_t sB  = sA + 2 * HALF_B;
        uint32_t sBl = sA + 3 * HALF_B;

        #pragma unroll
        for (int sub = 0; sub < 2; sub++) {
            uint32_t ko = (uint32_t)(sub * 32);
            uint32_t ahi[2][4], alo[2][4];
            #pragma unroll
            for (int mi = 0; mi < 2; mi++) {
                uint32_t ao_ = (uint32_t)(wm * 32 + mi * 16 + l15) * 80 + ko + lhi * 16;
                ldsm4(sA + ao_,  ahi[mi][0], ahi[mi][1], ahi[mi][2], ahi[mi][3]);
                ldsm4(sAl + ao_, alo[mi][0], alo[mi][1], alo[mi][2], alo[mi][3]);
            }
            #pragma unroll
            for (int p = 0; p < 4; p++) {
                uint32_t bo_ = (uint32_t)(wn * 64 + p * 16 + (g8 >> 1) * 8 + l7) * 80
                             + ko + (g8 & 1) * 16;
                uint32_t bh[4], bl[4];
                ldsm4(sB + bo_,  bh[0], bh[1], bh[2], bh[3]);
                ldsm4(sBl + bo_, bl[0], bl[1], bl[2], bl[3]);
                #pragma unroll
                for (int mi = 0; mi < 2; mi++) {
                    MMA_BF16(acc[mi][2 * p],     ahi[mi], bh[0], bh[1]);
                    MMA_BF16(acc[mi][2 * p],     ahi[mi], bl[0], bl[1]);
                    MMA_BF16(acc[mi][2 * p],     alo[mi], bh[0], bh[1]);
                    MMA_BF16(acc[mi][2 * p + 1], ahi[mi], bh[2], bh[3]);
                    MMA_BF16(acc[mi][2 * p + 1], ahi[mi], bl[2], bl[3]);
                    MMA_BF16(acc[mi][2 * p + 1], alo[mi], bh[2], bh[3]);
                }
            }
        }
        __syncthreads();
    }

    int colp = kq * 2;
    if (mode == 0) {
        #pragma unroll
        for (int ni = 0; ni < 8; ni++) {
            int rf = bx * 128 + wn * 64 + ni * 8 + colp;
            int t = rf / C_;
            int rem = rf - t * C_;
            int h = rem >> 6, d = rem & 63;
            #pragma unroll
            for (int mi = 0; mi < 2; mi++) {
                int mb = by * 128 + wm * 32 + mi * 16 + rq;
                #pragma unroll
                for (int rr = 0; rr < 2; rr++) {
                    int m = mb + rr * 8;
                    int n = m >> 10, s = m & 1023;
                    int nh = n * NH_ + h;
                    float v0 = acc[mi][ni][rr * 2], v1 = acc[mi][ni][rr * 2 + 1];
                    if (t == 0) {
                        *(float2*)(g_q + ((size_t)nh * S_ + s) * D_ + d) =
                            make_float2(v0 * 0.125f, v1 * 0.125f);
                    } else if (t == 1) {
                        float h0 = __bfloat162float(__float2bfloat16(v0));
                        float h1 = __bfloat162float(__float2bfloat16(v1));
                        size_t off = ((size_t)nh * S_ + s) * D_ + d;
                        *(uint32_t*)(g_kh + off) = bfpair(v0, v1);
                        *(uint32_t*)(g_kl + off) = bfpair(v0 - h0, v1 - h1);
                    } else {
                        float h0 = __bfloat162float(__float2bfloat16(v0));
                        float h1 = __bfloat162float(__float2bfloat16(v1));
                        size_t o0 = ((size_t)nh * D_ + d) * S_ + s;
                        g_vh[o0] = __float2bfloat16(v0);
                        g_vl[o0] = __float2bfloat16(v0 - h0);
                        g_vh[o0 + S_] = __float2bfloat16(v1);
                        g_vl[o0 + S_] = __float2bfloat16(v1 - h1);
                    }
                }
            }
        }
    } else {
        #pragma unroll
        for (int ni = 0; ni < 8; ni++) {
            int m = bx * 128 + wn * 64 + ni * 8 + colp;
            int n = m >> 10, s = m & 1023;
            #pragma unroll
            for (int mi = 0; mi < 2; mi++) {
                int cb = by * 128 + wm * 32 + mi * 16 + rq;
                #pragma unroll
                for (int rr = 0; rr < 2; rr++) {
                    int cc = cb + rr * 8;
                    float bb = bias[cc];
                    float2 v = make_float2(acc[mi][ni][rr * 2] + bb,
                                           acc[mi][ni][rr * 2 + 1] + bb);
                    *(float2*)(out + ((size_t)n * C_ + cc) * S_ + s) = v;
                }
            }
        }
    }
}

// ---------------- bf16x3 tensor-core flash attention (ldmatrix K/V) --------
#define AST 68
#define KVROW 144
#define KVTILE (64*KVROW)
#define ATT2_SMEM (34816 + 4*2*KVTILE)

__global__ __launch_bounds__(256) void attn_mma() {
    extern __shared__ __align__(16) char smc[];
    float* Pb = (float*)smc;
    uint32_t sb  = smem_u32(smc);
    uint32_t khS = sb + 34816;
    uint32_t klS = khS + 2 * KVTILE;
    uint32_t vhS = klS + 2 * KVTILE;
    uint32_t vlS = vhS + 2 * KVTILE;

    int tid = threadIdx.x;
    int lane = tid & 31, w = tid >> 5;
    int rq = lane >> 2, kq = lane & 3;
    int g8 = lane >> 3, l7 = lane & 7;
    int nh = blockIdx.y, q0 = blockIdx.x * 128;

    const float* qg = g_q  + ((size_t)nh * S_ + q0) * D_;
    const bf16* khg = g_kh + (size_t)nh * S_ * D_;
    const bf16* klg = g_kl + (size_t)nh * S_ * D_;
    const bf16* vhg = g_vh + (size_t)nh * D_ * S_;
    const bf16* vlg = g_vl + (size_t)nh * D_ * S_;

    #pragma unroll
    for (int i = 0; i < 8; i++) {
        int idx = i * 256 + tid;
        int r = idx >> 4, sg = idx & 15;
        cp16(smem_u32(&Pb[r * AST + sg * 4]), qg + (size_t)r * D_ + sg * 4);
    }
    CP_COMMIT();

    #pragma unroll
    for (int t = 0; t < 2; t++) {
        #pragma unroll
        for (int i = 0; i < 2; i++) {
            int idx = i * 256 + tid;
            int row = idx >> 3, sg = idx & 7;
            uint32_t so = (uint32_t)(t * KVTILE + row * KVROW) + sg * 16;
            cp16(khS + so, khg + (size_t)(t * 64 + row) * D_ + sg * 8);
            cp16(klS + so, klg + (size_t)(t * 64 + row) * D_ + sg * 8);
            cp16(vhS + so, vhg + (size_t)row * S_ + t * 64 + sg * 8);
            cp16(vlS + so, vlg + (size_t)row * S_ + t * 64 + sg * 8);
        }
        CP_COMMIT();
    }

    CP_WAIT2();
    __syncthreads();

    uint32_t qah[4][4], qal[4][4];
    {
        const float* qp = &Pb[(w * 16 + rq) * AST];
        #pragma unroll
        for (int s = 0; s < 4; s++) {
            int d0 = s * 16 + 2 * kq;
            bfsplit2(qp[d0],            qp[d0 + 1],            qah[s][0], qal[s][0]);
            bfsplit2(qp[8 * AST + d0],  qp[8 * AST + d0 + 1],  qah[s][1], qal[s][1]);
            bfsplit2(qp[d0 + 8],        qp[d0 + 9],            qah[s][2], qal[s][2]);
            bfsplit2(qp[8 * AST + d0 + 8], qp[8 * AST + d0 + 9], qah[s][3], qal[s][3]);
        }
    }
    __syncthreads();

    float o[8][4];
    #pragma unroll
    for (int n = 0; n < 8; n++)
        #pragma unroll
        for (int j = 0; j < 4; j++) o[n][j] = 0.0f;
    float m0 = -1e30f, m1 = -1e30f, l0 = 0.0f, l1 = 0.0f;

    for (int kt = 0; kt < 16; kt++) {
        if (kt < 15) { CP_WAIT1(); } else { CP_WAIT0(); }
        __syncthreads();
        uint32_t boff = (uint32_t)((kt & 1) * KVTILE);

        // ---- QK^T (3-pass bf16, ldmatrix) ----
        float acc[8][4];
        #pragma unroll
        for (int n = 0; n < 8; n++)
            #pragma unroll
            for (int j = 0; j < 4; j++) acc[n][j] = 0.0f;

        #pragma unroll
        for (int s = 0; s < 4; s++) {
            #pragma unroll
            for (int p = 0; p < 4; p++) {
                uint32_t bo = boff + (uint32_t)(p * 16 + (g8 >> 1) * 8 + l7) * KVROW
                            + s * 32 + (g8 & 1) * 16;
                uint32_t bh[4], bl[4];
                ldsm4(khS + bo, bh[0], bh[1], bh[2], bh[3]);
                ldsm4(klS + bo, bl[0], bl[1], bl[2], bl[3]);
                MMA_BF16(acc[2 * p],     qah[s], bh[0], bh[1]);
                MMA_BF16(acc[2 * p],     qah[s], bl[0], bl[1]);
                MMA_BF16(acc[2 * p],     qal[s], bh[0], bh[1]);
                MMA_BF16(acc[2 * p + 1], qah[s], bh[2], bh[3]);
                MMA_BF16(acc[2 * p + 1], qah[s], bl[2], bl[3]);
                MMA_BF16(acc[2 * p + 1], qal[s], bh[2], bh[3]);
            }
        }

        // ---- softmax ----
        float t0 = -1e30f, t1 = -1e30f;
        #pragma unroll
        for (int n = 0; n < 8; n++) {
            t0 = fmaxf(t0, fmaxf(acc[n][0], acc[n][1]));
            t1 = fmaxf(t1, fmaxf(acc[n][2], acc[n][3]));
        }
        t0 = fmaxf(t0, __shfl_xor_sync(0xffffffffu, t0, 1));
        t0 = fmaxf(t0, __shfl_xor_sync(0xffffffffu, t0, 2));
        t1 = fmaxf(t1, __shfl_xor_sync(0xffffffffu, t1, 1));
        t1 = fmaxf(t1, __shfl_xor_sync(0xffffffffu, t1, 2));
        float mn0 = fmaxf(m0, t0), mn1 = fmaxf(m1, t1);
        float c0 = __expf(m0 - mn0), c1 = __expf(m1 - mn1);
        m0 = mn0; m1 = mn1;
        l0 *= c0; l1 *= c1;
        #pragma unroll
        for (int n = 0; n < 8; n++) {
            o[n][0] *= c0; o[n][1] *= c0; o[n][2] *= c1; o[n][3] *= c1;
        }

        float* pr = &Pb[(w * 16 + rq) * AST + kq * 2];
        #pragma unroll
        for (int n = 0; n < 8; n++) {
            float p0 = __expf(acc[n][0] - m0), p1 = __expf(acc[n][1] - m0);
            float p2 = __expf(acc[n][2] - m1), p3 = __expf(acc[n][3] - m1);
            l0 += p0 + p1; l1 += p2 + p3;
            *(float2*)(pr + n * 8)           = make_float2(p0, p1);
            *(float2*)(pr + 8 * AST + n * 8) = make_float2(p2, p3);
        }
        __syncwarp();

        // ---- PV (3-pass bf16; P split in registers; ldmatrix V) ----
        const float* pa = &Pb[(w * 16 + rq) * AST];
        #pragma unroll
        for (int t4 = 0; t4 < 4; t4++) {
            int k0 = t4 * 16 + 2 * kq;
            uint32_t ph[4], pl[4];
            bfsplit2(pa[k0],           pa[k0 + 1],           ph[0], pl[0]);
            bfsplit2(pa[8 * AST + k0], pa[8 * AST + k0 + 1], ph[1], pl[1]);
            bfsplit2(pa[k0 + 8],       pa[k0 + 9],           ph[2], pl[2]);
            bfsplit2(pa[8 * AST + k0 + 8], pa[8 * AST + k0 + 9], ph[3], pl[3]);
            #pragma unroll
            for (int p = 0; p < 4; p++) {
                uint32_t bo = boff + (uint32_t)(p * 16 + (g8 >> 1) * 8 + l7) * KVROW
                            + t4 * 32 + (g8 & 1) * 16;
                uint32_t bh[4], bl[4];
                ldsm4(vhS + bo, bh[0], bh[1], bh[2], bh[3]);
                ldsm4(vlS + bo, bl[0], bl[1], bl[2], bl[3]);
                MMA_BF16(o[2 * p],     ph, bh[0], bh[1]);
                MMA_BF16(o[2 * p],     ph, bl[0], bl[1]);
                MMA_BF16(o[2 * p],     pl, bh[0], bh[1]);
                MMA_BF16(o[2 * p + 1], ph, bh[2], bh[3]);
                MMA_BF16(o[2 * p + 1], ph, bl[2], bl[3]);
                MMA_BF16(o[2 * p + 1], pl, bh[2], bh[3]);
            }
        }
        __syncthreads();

        if (kt + 2 < 16) {
            int t = kt + 2;
            #pragma unroll
            for (int i = 0; i < 2; i++) {
                int idx = i * 256 + tid;
                int row = idx >> 3, sg = idx & 7;
                uint32_t so = boff + (uint32_t)(row * KVROW) + sg * 16;
                cp16(khS + so, khg + (size_t)(t * 64 + row) * D_ + sg * 8);
                cp16(klS + so, klg + (size_t)(t * 64 + row) * D_ + sg * 8);
                cp16(vhS + so, vhg + (size_t)row * S_ + t * 64 + sg * 8);
                cp16(vlS + so, vlg + (size_t)row * S_ + t * 64 + sg * 8);
            }
            CP_COMMIT();
        }
    }

    l0 += __shfl_xor_sync(0xffffffffu, l0, 1);
    l0 += __shfl_xor_sync(0xffffffffu, l0, 2);
    l1 += __shfl_xor_sync(0xffffffffu, l1, 1);
    l1 += __shfl_xor_sync(0xffffffffu, l1, 2);
    float i0 = 1.0f / l0, i1 = 1.0f / l1;
    int nb = nh / NH_, hh = nh % NH_;
    int r0g = q0 + w * 16 + rq;
    size_t m0r = (size_t)(nb * S_ + r0g) * C_ + hh * 64 + kq * 2;
    size_t m1r = m0r + (size_t)8 * C_;
    #pragma unroll
    for (int n = 0; n < 8; n++) {
        float a0 = o[n][0] * i0, a1 = o[n][1] * i0;
        float b0 = o[n][2] * i1, b1 = o[n][3] * i1;
        uint32_t h, l;
        bfsplit2(a0, a1, h, l);
        *(uint32_t*)(g_ao_hi + m0r + n * 8) = h;
        *(uint32_t*)(g_ao_lo + m0r + n * 8) = l;
        bfsplit2(b0, b1, h, l);
        *(uint32_t*)(g_ao_hi + m1r + n * 8) = h;
        *(uint32_t*)(g_ao_lo + m1r + n * 8) = l;
    }
}

// ---------------- launch ----------------
extern "C" void kernel_launch(void* const* d_in, const int* in_sizes, int n_in,
                              void* d_out, int out_size) {
    const float* x     = (const float*)d_in[0];
    const float* w_qkv = (const float*)d_in[1];
    const float* w_out = (const float*)d_in[2];
    const float* b_out = (const float*)d_in[3];
    float* out = (float*)d_out;

    cudaFuncSetAttribute(mma_gemm, cudaFuncAttributeMaxDynamicSharedMemorySize, GEMM_SMEM);
    cudaFuncSetAttribute(attn_mma, cudaFuncAttributeMaxDynamicSharedMemorySize, ATT2_SMEM);

    transpose_x<<<dim3(S_ / 32, C_ / 32, N_), dim3(32, 8)>>>(x);
    split_wqkv<<<(C3_ * C_ + 255) / 256, 256>>>(w_qkv);
    split_wout<<<(C_ * C_ + 255) / 256, 256>>>(w_out);

    mma_gemm<<<dim3(C3_ / 128, M_ / 128), 256, GEMM_SMEM>>>(0, nullptr, nullptr);

    attn_mma<<<dim3(S_ / 128, N_ * NH_), 256, ATT2_SMEM>>>();

    mma_gemm<<<dim3(M_ / 128, C_ / 128), 256, GEMM_SMEM>>>(1, b_out, out);
}

// round 13
// speedup vs baseline: 1.2146x; 1.2146x over previous
#include <cuda_runtime.h>
#include <cuda_bf16.h>
#include <cuda_fp16.h>
#include <cstdint>

#define N_   16
#define C_   384
#define S_   1024
#define NH_  6
#define D_   64
#define C3_  1152
#define M_   (N_*S_)

typedef __nv_bfloat16 bf16;

__device__ bf16 g_tok_hi[M_*C_],  g_tok_lo[M_*C_];
__device__ bf16 g_wqkv_hi[C3_*C_], g_wqkv_lo[C3_*C_];
__device__ bf16 g_wout_hi[C_*C_],  g_wout_lo[C_*C_];
__device__ __half g_qh[N_*NH_*S_*D_];                  // fp16, 0.125 folded
__device__ __half g_kh[N_*NH_*S_*D_];                  // fp16
__device__ bf16 g_vh[N_*NH_*D_*S_], g_vl[N_*NH_*D_*S_];   // V^T [nh][d][s]
__device__ bf16 g_ao_hi[M_*C_], g_ao_lo[M_*C_];

__device__ __forceinline__ uint32_t smem_u32(const void* p) {
    uint32_t a;
    asm("{ .reg .u64 t; cvta.to.shared.u64 t, %1; cvt.u32.u64 %0, t; }" : "=r"(a) : "l"(p));
    return a;
}
__device__ __forceinline__ void ldsm4(uint32_t a, uint32_t& r0, uint32_t& r1,
                                      uint32_t& r2, uint32_t& r3) {
    asm volatile("ldmatrix.sync.aligned.m8n8.x4.shared.b16 {%0,%1,%2,%3}, [%4];"
        : "=r"(r0), "=r"(r1), "=r"(r2), "=r"(r3) : "r"(a));
}
__device__ __forceinline__ void cp16(uint32_t saddr, const void* g) {
    size_t ga = __cvta_generic_to_global(g);
    asm volatile("cp.async.cg.shared.global [%0], [%1], 16;" :: "r"(saddr), "l"(ga) : "memory");
}
#define CP_COMMIT() asm volatile("cp.async.commit_group;" ::: "memory")
#define CP_WAIT0()  asm volatile("cp.async.wait_group 0;" ::: "memory")
#define CP_WAIT1()  asm volatile("cp.async.wait_group 1;" ::: "memory")
#define CP_WAIT2()  asm volatile("cp.async.wait_group 2;" ::: "memory")

__device__ __forceinline__ uint32_t bfpair(float a, float b) {
    __nv_bfloat162 t; t.x = __float2bfloat16(a); t.y = __float2bfloat16(b);
    return *(uint32_t*)&t;
}
__device__ __forceinline__ void bfsplit2(float a, float b, uint32_t& h, uint32_t& l) {
    bf16 ha = __float2bfloat16(a), hb = __float2bfloat16(b);
    __nv_bfloat162 hp; hp.x = ha; hp.y = hb;
    h = *(uint32_t*)&hp;
    l = bfpair(a - __bfloat162float(ha), b - __bfloat162float(hb));
}
__device__ __forceinline__ uint32_t hpair(float a, float b) {
    __half2 t = __floats2half2_rn(a, b);
    return *(uint32_t*)&t;
}

#define MMA_BF16(d, a, b0, b1)                                                \
    asm volatile("mma.sync.aligned.m16n8k16.row.col.f32.bf16.bf16.f32 "       \
        "{%0,%1,%2,%3}, {%4,%5,%6,%7}, {%8,%9}, {%0,%1,%2,%3};"               \
        : "+f"((d)[0]), "+f"((d)[1]), "+f"((d)[2]), "+f"((d)[3])              \
        : "r"((a)[0]), "r"((a)[1]), "r"((a)[2]), "r"((a)[3]),                 \
          "r"(b0), "r"(b1))
#define MMA_F16(d, a, b0, b1)                                                 \
    asm volatile("mma.sync.aligned.m16n8k16.row.col.f32.f16.f16.f32 "         \
        "{%0,%1,%2,%3}, {%4,%5,%6,%7}, {%8,%9}, {%0,%1,%2,%3};"               \
        : "+f"((d)[0]), "+f"((d)[1]), "+f"((d)[2]), "+f"((d)[3])              \
        : "r"((a)[0]), "r"((a)[1]), "r"((a)[2]), "r"((a)[3]),                 \
          "r"(b0), "r"(b1))

// ---------------- input prep ----------------
__global__ void transpose_x(const float* __restrict__ x) {
    __shared__ float t[32][33];
    int n = blockIdx.z, k0 = blockIdx.y * 32, s0 = blockIdx.x * 32;
    int tx = threadIdx.x, ty = threadIdx.y;
    const float* src = x + ((size_t)n * C_ + k0) * S_ + s0;
    #pragma unroll
    for (int j = 0; j < 4; j++)
        t[ty + 8 * j][tx] = src[(size_t)(ty + 8 * j) * S_ + tx];
    __syncthreads();
    size_t base = ((size_t)n * S_ + s0) * C_ + k0;
    #pragma unroll
    for (int j = 0; j < 4; j++) {
        float a = t[tx][ty + 8 * j];
        bf16 h = __float2bfloat16(a);
        size_t o = base + (size_t)(ty + 8 * j) * C_ + tx;
        g_tok_hi[o] = h;
        g_tok_lo[o] = __float2bfloat16(a - __bfloat162float(h));
    }
}
__global__ void split_wqkv(const float* __restrict__ w) {
    int i = blockIdx.x * 256 + threadIdx.x;
    if (i < C3_ * C_) {
        float a = w[i]; bf16 h = __float2bfloat16(a);
        g_wqkv_hi[i] = h; g_wqkv_lo[i] = __float2bfloat16(a - __bfloat162float(h));
    }
}
__global__ void split_wout(const float* __restrict__ w) {
    int i = blockIdx.x * 256 + threadIdx.x;
    if (i < C_ * C_) {
        float a = w[i]; bf16 h = __float2bfloat16(a);
        g_wout_hi[i] = h; g_wout_lo[i] = __float2bfloat16(a - __bfloat162float(h));
    }
}

// ---------------- 3xBF16 mma.sync GEMM (2-stage, KCH=32, ldmatrix) --------
#define KCH 32
#define HALF_B (128*80)
#define STAGE_B (4*HALF_B)
#define GEMM_SMEM (2*STAGE_B)

__global__ __launch_bounds__(256) void mma_gemm(
    int mode, const float* __restrict__ bias, float* __restrict__ out)
{
    extern __shared__ __align__(16) char smem[];
    uint32_t sbase = smem_u32(smem);
    int tid = threadIdx.x;
    int lane = tid & 31, w = tid >> 5;
    int wm = w & 3, wn = w >> 2;
    int by = blockIdx.y, bx = blockIdx.x;
    int rq = lane >> 2, kq = lane & 3;
    int l15 = lane & 15, lhi = lane >> 4;
    int g8 = lane >> 3, l7 = lane & 7;

    const bf16 *Ahp, *Alp, *Bhp, *Blp;
    if (mode == 0) { Ahp = g_tok_hi;  Alp = g_tok_lo;  Bhp = g_wqkv_hi; Blp = g_wqkv_lo; }
    else           { Ahp = g_wout_hi; Alp = g_wout_lo; Bhp = g_ao_hi;   Blp = g_ao_lo; }
    const bf16* Ah = Ahp + (size_t)by * 128 * C_;
    const bf16* Al = Alp + (size_t)by * 128 * C_;
    const bf16* Bh = Bhp + (size_t)bx * 128 * C_;
    const bf16* Bl = Blp + (size_t)bx * 128 * C_;

    float acc[2][8][4];
    #pragma unroll
    for (int i = 0; i < 2; i++)
        #pragma unroll
        for (int j = 0; j < 8; j++)
            #pragma unroll
            for (int q = 0; q < 4; q++) acc[i][j][q] = 0.0f;

    auto issue = [&](int c, int st) {
        uint32_t s0 = sbase + st * STAGE_B;
        #pragma unroll
        for (int i = 0; i < 2; i++) {
            int idx = i * 256 + tid;
            int row = idx >> 2, seg = idx & 3;
            size_t go = (size_t)row * C_ + c * KCH + seg * 8;
            uint32_t so = row * 80 + seg * 16;
            cp16(s0 + so,              Ah + go);
            cp16(s0 + HALF_B + so,     Al + go);
            cp16(s0 + 2 * HALF_B + so, Bh + go);
            cp16(s0 + 3 * HALF_B + so, Bl + go);
        }
        CP_COMMIT();
    };

    const int NCH = C_ / KCH;   // 12
    issue(0, 0);
    for (int c = 0; c < NCH; c++) {
        int st = c & 1;
        if (c + 1 < NCH) { issue(c + 1, st ^ 1); CP_WAIT1(); }
        else             { CP_WAIT0(); }
        __syncthreads();

        uint32_t sA  = sbase + st * STAGE_B;
        uint32_t sAl = sA + HALF_B;
        uint32_t sB  = sA + 2 * HALF_B;
        uint32_t sBl = sA + 3 * HALF_B;

        #pragma unroll
        for (int sub = 0; sub < 2; sub++) {
            uint32_t ko = (uint32_t)(sub * 32);
            uint32_t ahi[2][4], alo[2][4];
            #pragma unroll
            for (int mi = 0; mi < 2; mi++) {
                uint32_t ao_ = (uint32_t)(wm * 32 + mi * 16 + l15) * 80 + ko + lhi * 16;
                ldsm4(sA + ao_,  ahi[mi][0], ahi[mi][1], ahi[mi][2], ahi[mi][3]);
                ldsm4(sAl + ao_, alo[mi][0], alo[mi][1], alo[mi][2], alo[mi][3]);
            }
            #pragma unroll
            for (int p = 0; p < 4; p++) {
                uint32_t bo_ = (uint32_t)(wn * 64 + p * 16 + (g8 >> 1) * 8 + l7) * 80
                             + ko + (g8 & 1) * 16;
                uint32_t bh[4], bl[4];
                ldsm4(sB + bo_,  bh[0], bh[1], bh[2], bh[3]);
                ldsm4(sBl + bo_, bl[0], bl[1], bl[2], bl[3]);
                #pragma unroll
                for (int mi = 0; mi < 2; mi++) {
                    MMA_BF16(acc[mi][2 * p],     ahi[mi], bh[0], bh[1]);
                    MMA_BF16(acc[mi][2 * p],     ahi[mi], bl[0], bl[1]);
                    MMA_BF16(acc[mi][2 * p],     alo[mi], bh[0], bh[1]);
                    MMA_BF16(acc[mi][2 * p + 1], ahi[mi], bh[2], bh[3]);
                    MMA_BF16(acc[mi][2 * p + 1], ahi[mi], bl[2], bl[3]);
                    MMA_BF16(acc[mi][2 * p + 1], alo[mi], bh[2], bh[3]);
                }
            }
        }
        __syncthreads();
    }

    int colp = kq * 2;
    if (mode == 0) {
        #pragma unroll
        for (int ni = 0; ni < 8; ni++) {
            int rf = bx * 128 + wn * 64 + ni * 8 + colp;
            int t = rf / C_;
            int rem = rf - t * C_;
            int h = rem >> 6, d = rem & 63;
            #pragma unroll
            for (int mi = 0; mi < 2; mi++) {
                int mb = by * 128 + wm * 32 + mi * 16 + rq;
                #pragma unroll
                for (int rr = 0; rr < 2; rr++) {
                    int m = mb + rr * 8;
                    int n = m >> 10, s = m & 1023;
                    int nh = n * NH_ + h;
                    float v0 = acc[mi][ni][rr * 2], v1 = acc[mi][ni][rr * 2 + 1];
                    if (t == 0) {
                        *(uint32_t*)(g_qh + ((size_t)nh * S_ + s) * D_ + d) =
                            hpair(v0 * 0.125f, v1 * 0.125f);
                    } else if (t == 1) {
                        *(uint32_t*)(g_kh + ((size_t)nh * S_ + s) * D_ + d) =
                            hpair(v0, v1);
                    } else {
                        float h0 = __bfloat162float(__float2bfloat16(v0));
                        float h1 = __bfloat162float(__float2bfloat16(v1));
                        size_t o0 = ((size_t)nh * D_ + d) * S_ + s;
                        g_vh[o0] = __float2bfloat16(v0);
                        g_vl[o0] = __float2bfloat16(v0 - h0);
                        g_vh[o0 + S_] = __float2bfloat16(v1);
                        g_vl[o0 + S_] = __float2bfloat16(v1 - h1);
                    }
                }
            }
        }
    } else {
        #pragma unroll
        for (int ni = 0; ni < 8; ni++) {
            int m = bx * 128 + wn * 64 + ni * 8 + colp;
            int n = m >> 10, s = m & 1023;
            #pragma unroll
            for (int mi = 0; mi < 2; mi++) {
                int cb = by * 128 + wm * 32 + mi * 16 + rq;
                #pragma unroll
                for (int rr = 0; rr < 2; rr++) {
                    int cc = cb + rr * 8;
                    float bb = bias[cc];
                    float2 v = make_float2(acc[mi][ni][rr * 2] + bb,
                                           acc[mi][ni][rr * 2 + 1] + bb);
                    *(float2*)(out + ((size_t)n * C_ + cc) * S_ + s) = v;
                }
            }
        }
    }
}

// ---------------- flash attention: fp16 1-pass QK, bf16x3 PV ----------------
// 256 thr; warp w owns q rows [w*16, w*16+16). 64-key tiles, 16 iters.
// Q fp16 resident in registers (ldmatrix); K fp16 single array; V bf16 hi/lo.
#define AST 68
#define KVROW 144
#define KVTILE (64*KVROW)          // 9216 B
#define ATT2_SMEM (34816 + 3*2*KVTILE)   // Pb(fp32 P / fp16 Q staging) + K,Vh,Vl x2

__global__ __launch_bounds__(256) void attn_mma() {
    extern __shared__ __align__(16) char smc[];
    float* Pb = (float*)smc;                 // [128][68] fp32 P; Q fp16 staging first
    uint32_t sb  = smem_u32(smc);
    uint32_t khS = sb + 34816;
    uint32_t vhS = khS + 2 * KVTILE;
    uint32_t vlS = vhS + 2 * KVTILE;

    int tid = threadIdx.x;
    int lane = tid & 31, w = tid >> 5;
    int rq = lane >> 2, kq = lane & 3;
    int l15 = lane & 15, lhi = lane >> 4;
    int g8 = lane >> 3, l7 = lane & 7;
    int nh = blockIdx.y, q0 = blockIdx.x * 128;

    const __half* qhg = g_qh + ((size_t)nh * S_ + q0) * D_;
    const __half* khg = g_kh + (size_t)nh * S_ * D_;
    const bf16*   vhg = g_vh + (size_t)nh * D_ * S_;
    const bf16*   vlg = g_vl + (size_t)nh * D_ * S_;

    // group 1: Q fp16 -> Pb region ([128][72 halves], 144B rows)
    #pragma unroll
    for (int i = 0; i < 4; i++) {
        int idx = i * 256 + tid;
        int r = idx >> 3, sg = idx & 7;
        cp16(sb + (uint32_t)r * KVROW + sg * 16, qhg + (size_t)r * D_ + sg * 8);
    }
    CP_COMMIT();

    // groups 2,3: K/Vh/Vl tiles 0,1
    #pragma unroll
    for (int t = 0; t < 2; t++) {
        #pragma unroll
        for (int i = 0; i < 2; i++) {
            int idx = i * 256 + tid;
            int row = idx >> 3, sg = idx & 7;
            uint32_t so = (uint32_t)(t * KVTILE + row * KVROW) + sg * 16;
            cp16(khS + so, khg + (size_t)(t * 64 + row) * D_ + sg * 8);
            cp16(vhS + so, vhg + (size_t)row * S_ + t * 64 + sg * 8);
            cp16(vlS + so, vlg + (size_t)row * S_ + t * 64 + sg * 8);
        }
        CP_COMMIT();
    }

    CP_WAIT2();
    __syncthreads();

    // Q fragments via ldmatrix (fp16, no split)
    uint32_t qfr[4][4];
    #pragma unroll
    for (int s = 0; s < 4; s++) {
        uint32_t ao = sb + (uint32_t)(w * 16 + l15) * KVROW + s * 32 + lhi * 16;
        ldsm4(ao, qfr[s][0], qfr[s][1], qfr[s][2], qfr[s][3]);
    }
    __syncthreads();     // Pb region now reusable for P

    float o[8][4];
    #pragma unroll
    for (int n = 0; n < 8; n++)
        #pragma unroll
        for (int j = 0; j < 4; j++) o[n][j] = 0.0f;
    float m0 = -1e30f, m1 = -1e30f, l0 = 0.0f, l1 = 0.0f;

    for (int kt = 0; kt < 16; kt++) {
        if (kt < 15) { CP_WAIT1(); } else { CP_WAIT0(); }
        __syncthreads();
        uint32_t boff = (uint32_t)((kt & 1) * KVTILE);

        // ---- QK^T: single-pass fp16 ----
        float acc[8][4];
        #pragma unroll
        for (int n = 0; n < 8; n++)
            #pragma unroll
            for (int j = 0; j < 4; j++) acc[n][j] = 0.0f;

        #pragma unroll
        for (int s = 0; s < 4; s++) {
            #pragma unroll
            for (int p = 0; p < 4; p++) {
                uint32_t bo = boff + (uint32_t)(p * 16 + (g8 >> 1) * 8 + l7) * KVROW
                            + s * 32 + (g8 & 1) * 16;
                uint32_t b0, b1, b2, b3;
                ldsm4(khS + bo, b0, b1, b2, b3);
                MMA_F16(acc[2 * p],     qfr[s], b0, b1);
                MMA_F16(acc[2 * p + 1], qfr[s], b2, b3);
            }
        }

        // ---- softmax ----
        float t0 = -1e30f, t1 = -1e30f;
        #pragma unroll
        for (int n = 0; n < 8; n++) {
            t0 = fmaxf(t0, fmaxf(acc[n][0], acc[n][1]));
            t1 = fmaxf(t1, fmaxf(acc[n][2], acc[n][3]));
        }
        t0 = fmaxf(t0, __shfl_xor_sync(0xffffffffu, t0, 1));
        t0 = fmaxf(t0, __shfl_xor_sync(0xffffffffu, t0, 2));
        t1 = fmaxf(t1, __shfl_xor_sync(0xffffffffu, t1, 1));
        t1 = fmaxf(t1, __shfl_xor_sync(0xffffffffu, t1, 2));
        float mn0 = fmaxf(m0, t0), mn1 = fmaxf(m1, t1);
        float c0 = __expf(m0 - mn0), c1 = __expf(m1 - mn1);
        m0 = mn0; m1 = mn1;
        l0 *= c0; l1 *= c1;
        #pragma unroll
        for (int n = 0; n < 8; n++) {
            o[n][0] *= c0; o[n][1] *= c0; o[n][2] *= c1; o[n][3] *= c1;
        }

        float* pr = &Pb[(w * 16 + rq) * AST + kq * 2];
        #pragma unroll
        for (int n = 0; n < 8; n++) {
            float p0 = __expf(acc[n][0] - m0), p1 = __expf(acc[n][1] - m0);
            float p2 = __expf(acc[n][2] - m1), p3 = __expf(acc[n][3] - m1);
            l0 += p0 + p1; l1 += p2 + p3;
            *(float2*)(pr + n * 8)           = make_float2(p0, p1);
            *(float2*)(pr + 8 * AST + n * 8) = make_float2(p2, p3);
        }
        __syncwarp();

        // ---- PV: 3-pass bf16 (P split in registers; ldmatrix V) ----
        const float* pa = &Pb[(w * 16 + rq) * AST];
        #pragma unroll
        for (int t4 = 0; t4 < 4; t4++) {
            int k0 = t4 * 16 + 2 * kq;
            uint32_t ph[4], pl[4];
            bfsplit2(pa[k0],           pa[k0 + 1],           ph[0], pl[0]);
            bfsplit2(pa[8 * AST + k0], pa[8 * AST + k0 + 1], ph[1], pl[1]);
            bfsplit2(pa[k0 + 8],       pa[k0 + 9],           ph[2], pl[2]);
            bfsplit2(pa[8 * AST + k0 + 8], pa[8 * AST + k0 + 9], ph[3], pl[3]);
            #pragma unroll
            for (int p = 0; p < 4; p++) {
                uint32_t bo = boff + (uint32_t)(p * 16 + (g8 >> 1) * 8 + l7) * KVROW
                            + t4 * 32 + (g8 & 1) * 16;
                uint32_t bh[4], bl[4];
                ldsm4(vhS + bo, bh[0], bh[1], bh[2], bh[3]);
                ldsm4(vlS + bo, bl[0], bl[1], bl[2], bl[3]);
                MMA_BF16(o[2 * p],     ph, bh[0], bh[1]);
                MMA_BF16(o[2 * p],     ph, bl[0], bl[1]);
                MMA_BF16(o[2 * p],     pl, bh[0], bh[1]);
                MMA_BF16(o[2 * p + 1], ph, bh[2], bh[3]);
                MMA_BF16(o[2 * p + 1], ph, bl[2], bl[3]);
                MMA_BF16(o[2 * p + 1], pl, bh[2], bh[3]);
            }
        }
        __syncthreads();

        if (kt + 2 < 16) {
            int t = kt + 2;
            #pragma unroll
            for (int i = 0; i < 2; i++) {
                int idx = i * 256 + tid;
                int row = idx >> 3, sg = idx & 7;
                uint32_t so = boff + (uint32_t)(row * KVROW) + sg * 16;
                cp16(khS + so, khg + (size_t)(t * 64 + row) * D_ + sg * 8);
                cp16(vhS + so, vhg + (size_t)row * S_ + t * 64 + sg * 8);
                cp16(vlS + so, vlg + (size_t)row * S_ + t * 64 + sg * 8);
            }
            CP_COMMIT();
        }
    }

    // ---- epilogue: normalize + bf16 hi/lo split -> g_ao_hi/lo ----
    l0 += __shfl_xor_sync(0xffffffffu, l0, 1);
    l0 += __shfl_xor_sync(0xffffffffu, l0, 2);
    l1 += __shfl_xor_sync(0xffffffffu, l1, 1);
    l1 += __shfl_xor_sync(0xffffffffu, l1, 2);
    float i0 = 1.0f / l0, i1 = 1.0f / l1;
    int nb = nh / NH_, hh = nh % NH_;
    int r0g = q0 + w * 16 + rq;
    size_t m0r = (size_t)(nb * S_ + r0g) * C_ + hh * 64 + kq * 2;
    size_t m1r = m0r + (size_t)8 * C_;
    #pragma unroll
    for (int n = 0; n < 8; n++) {
        float a0 = o[n][0] * i0, a1 = o[n][1] * i0;
        float b0 = o[n][2] * i1, b1 = o[n][3] * i1;
        uint32_t h, l;
        bfsplit2(a0, a1, h, l);
        *(uint32_t*)(g_ao_hi + m0r + n * 8) = h;
        *(uint32_t*)(g_ao_lo + m0r + n * 8) = l;
        bfsplit2(b0, b1, h, l);
        *(uint32_t*)(g_ao_hi + m1r + n * 8) = h;
        *(uint32_t*)(g_ao_lo + m1r + n * 8) = l;
    }
}

// ---------------- launch ----------------
extern "C" void kernel_launch(void* const* d_in, const int* in_sizes, int n_in,
                              void* d_out, int out_size) {
    const float* x     = (const float*)d_in[0];
    const float* w_qkv = (const float*)d_in[1];
    const float* w_out = (const float*)d_in[2];
    const float* b_out = (const float*)d_in[3];
    float* out = (float*)d_out;

    cudaFuncSetAttribute(mma_gemm, cudaFuncAttributeMaxDynamicSharedMemorySize, GEMM_SMEM);
    cudaFuncSetAttribute(attn_mma, cudaFuncAttributeMaxDynamicSharedMemorySize, ATT2_SMEM);

    transpose_x<<<dim3(S_ / 32, C_ / 32, N_), dim3(32, 8)>>>(x);
    split_wqkv<<<(C3_ * C_ + 255) / 256, 256>>>(w_qkv);
    split_wout<<<(C_ * C_ + 255) / 256, 256>>>(w_out);

    mma_gemm<<<dim3(C3_ / 128, M_ / 128), 256, GEMM_SMEM>>>(0, nullptr, nullptr);

    attn_mma<<<dim3(S_ / 128, N_ * NH_), 256, ATT2_SMEM>>>();

    mma_gemm<<<dim3(M_ / 128, C_ / 128), 256, GEMM_SMEM>>>(1, b_out, out);
}

// round 14
// speedup vs baseline: 1.5633x; 1.2871x over previous
#include <cuda_runtime.h>
#include <cuda_bf16.h>
#include <cuda_fp16.h>
#include <cstdint>

#define N_   16
#define C_   384
#define S_   1024
#define NH_  6
#define D_   64
#define C3_  1152
#define M_   (N_*S_)

typedef __nv_bfloat16 bf16;

__device__ bf16 g_tok_hi[M_*C_],  g_tok_lo[M_*C_];
__device__ bf16 g_wqkv_hi[C3_*C_], g_wqkv_lo[C3_*C_];
__device__ bf16 g_wout_hi[C_*C_],  g_wout_lo[C_*C_];
__device__ __half g_qh[N_*NH_*S_*D_];                  // fp16, 0.125 folded
__device__ __half g_kh[N_*NH_*S_*D_];                  // fp16
__device__ __half g_v[N_*NH_*D_*S_];                   // V^T fp16 [nh][d][s]
__device__ bf16 g_ao_hi[M_*C_], g_ao_lo[M_*C_];

__device__ __forceinline__ uint32_t smem_u32(const void* p) {
    uint32_t a;
    asm("{ .reg .u64 t; cvta.to.shared.u64 t, %1; cvt.u32.u64 %0, t; }" : "=r"(a) : "l"(p));
    return a;
}
__device__ __forceinline__ uint32_t lds32(uint32_t a) {
    uint32_t v; asm volatile("ld.shared.b32 %0, [%1];" : "=r"(v) : "r"(a)); return v;
}
__device__ __forceinline__ void sts32(uint32_t a, uint32_t v) {
    asm volatile("st.shared.b32 [%0], %1;" :: "r"(a), "r"(v) : "memory");
}
__device__ __forceinline__ void ldsm4(uint32_t a, uint32_t& r0, uint32_t& r1,
                                      uint32_t& r2, uint32_t& r3) {
    asm volatile("ldmatrix.sync.aligned.m8n8.x4.shared.b16 {%0,%1,%2,%3}, [%4];"
        : "=r"(r0), "=r"(r1), "=r"(r2), "=r"(r3) : "r"(a));
}
__device__ __forceinline__ void cp16(uint32_t saddr, const void* g) {
    size_t ga = __cvta_generic_to_global(g);
    asm volatile("cp.async.cg.shared.global [%0], [%1], 16;" :: "r"(saddr), "l"(ga) : "memory");
}
#define CP_COMMIT() asm volatile("cp.async.commit_group;" ::: "memory")
#define CP_WAIT0()  asm volatile("cp.async.wait_group 0;" ::: "memory")
#define CP_WAIT1()  asm volatile("cp.async.wait_group 1;" ::: "memory")
#define CP_WAIT2()  asm volatile("cp.async.wait_group 2;" ::: "memory")

__device__ __forceinline__ uint32_t bfpair(float a, float b) {
    __nv_bfloat162 t; t.x = __float2bfloat16(a); t.y = __float2bfloat16(b);
    return *(uint32_t*)&t;
}
__device__ __forceinline__ void bfsplit2(float a, float b, uint32_t& h, uint32_t& l) {
    bf16 ha = __float2bfloat16(a), hb = __float2bfloat16(b);
    __nv_bfloat162 hp; hp.x = ha; hp.y = hb;
    h = *(uint32_t*)&hp;
    l = bfpair(a - __bfloat162float(ha), b - __bfloat162float(hb));
}
__device__ __forceinline__ uint32_t hpair(float a, float b) {
    __half2 t = __floats2half2_rn(a, b);
    return *(uint32_t*)&t;
}

#define MMA_BF16(d, a, b0, b1)                                                \
    asm volatile("mma.sync.aligned.m16n8k16.row.col.f32.bf16.bf16.f32 "       \
        "{%0,%1,%2,%3}, {%4,%5,%6,%7}, {%8,%9}, {%0,%1,%2,%3};"               \
        : "+f"((d)[0]), "+f"((d)[1]), "+f"((d)[2]), "+f"((d)[3])              \
        : "r"((a)[0]), "r"((a)[1]), "r"((a)[2]), "r"((a)[3]),                 \
          "r"(b0), "r"(b1))
#define MMA_F16(d, a, b0, b1)                                                 \
    asm volatile("mma.sync.aligned.m16n8k16.row.col.f32.f16.f16.f32 "         \
        "{%0,%1,%2,%3}, {%4,%5,%6,%7}, {%8,%9}, {%0,%1,%2,%3};"               \
        : "+f"((d)[0]), "+f"((d)[1]), "+f"((d)[2]), "+f"((d)[3])              \
        : "r"((a)[0]), "r"((a)[1]), "r"((a)[2]), "r"((a)[3]),                 \
          "r"(b0), "r"(b1))

// ---------------- input prep ----------------
__global__ void transpose_x(const float* __restrict__ x) {
    __shared__ float t[32][33];
    int n = blockIdx.z, k0 = blockIdx.y * 32, s0 = blockIdx.x * 32;
    int tx = threadIdx.x, ty = threadIdx.y;
    const float* src = x + ((size_t)n * C_ + k0) * S_ + s0;
    #pragma unroll
    for (int j = 0; j < 4; j++)
        t[ty + 8 * j][tx] = src[(size_t)(ty + 8 * j) * S_ + tx];
    __syncthreads();
    size_t base = ((size_t)n * S_ + s0) * C_ + k0;
    #pragma unroll
    for (int j = 0; j < 4; j++) {
        float a = t[tx][ty + 8 * j];
        bf16 h = __float2bfloat16(a);
        size_t o = base + (size_t)(ty + 8 * j) * C_ + tx;
        g_tok_hi[o] = h;
        g_tok_lo[o] = __float2bfloat16(a - __bfloat162float(h));
    }
}
__global__ void split_wqkv(const float* __restrict__ w) {
    int i = blockIdx.x * 256 + threadIdx.x;
    if (i < C3_ * C_) {
        float a = w[i]; bf16 h = __float2bfloat16(a);
        g_wqkv_hi[i] = h; g_wqkv_lo[i] = __float2bfloat16(a - __bfloat162float(h));
    }
}
__global__ void split_wout(const float* __restrict__ w) {
    int i = blockIdx.x * 256 + threadIdx.x;
    if (i < C_ * C_) {
        float a = w[i]; bf16 h = __float2bfloat16(a);
        g_wout_hi[i] = h; g_wout_lo[i] = __float2bfloat16(a - __bfloat162float(h));
    }
}

// ---------------- 3xBF16 mma.sync GEMM (2-stage, KCH=32, ldmatrix) --------
#define KCH 32
#define HALF_B (128*80)
#define STAGE_B (4*HALF_B)
#define GEMM_SMEM (2*STAGE_B)

__global__ __launch_bounds__(256) void mma_gemm(
    int mode, const float* __restrict__ bias, float* __restrict__ out)
{
    extern __shared__ __align__(16) char smem[];
    uint32_t sbase = smem_u32(smem);
    int tid = threadIdx.x;
    int lane = tid & 31, w = tid >> 5;
    int wm = w & 3, wn = w >> 2;
    int by = blockIdx.y, bx = blockIdx.x;
    int rq = lane >> 2, kq = lane & 3;
    int l15 = lane & 15, lhi = lane >> 4;
    int g8 = lane >> 3, l7 = lane & 7;

    const bf16 *Ahp, *Alp, *Bhp, *Blp;
    if (mode == 0) { Ahp = g_tok_hi;  Alp = g_tok_lo;  Bhp = g_wqkv_hi; Blp = g_wqkv_lo; }
    else           { Ahp = g_wout_hi; Alp = g_wout_lo; Bhp = g_ao_hi;   Blp = g_ao_lo; }
    const bf16* Ah = Ahp + (size_t)by * 128 * C_;
    const bf16* Al = Alp + (size_t)by * 128 * C_;
    const bf16* Bh = Bhp + (size_t)bx * 128 * C_;
    const bf16* Bl = Blp + (size_t)bx * 128 * C_;

    float acc[2][8][4];
    #pragma unroll
    for (int i = 0; i < 2; i++)
        #pragma unroll
        for (int j = 0; j < 8; j++)
            #pragma unroll
            for (int q = 0; q < 4; q++) acc[i][j][q] = 0.0f;

    auto issue = [&](int c, int st) {
        uint32_t s0 = sbase + st * STAGE_B;
        #pragma unroll
        for (int i = 0; i < 2; i++) {
            int idx = i * 256 + tid;
            int row = idx >> 2, seg = idx & 3;
            size_t go = (size_t)row * C_ + c * KCH + seg * 8;
            uint32_t so = row * 80 + seg * 16;
            cp16(s0 + so,              Ah + go);
            cp16(s0 + HALF_B + so,     Al + go);
            cp16(s0 + 2 * HALF_B + so, Bh + go);
            cp16(s0 + 3 * HALF_B + so, Bl + go);
        }
        CP_COMMIT();
    };

    const int NCH = C_ / KCH;   // 12
    issue(0, 0);
    for (int c = 0; c < NCH; c++) {
        int st = c & 1;
        if (c + 1 < NCH) { issue(c + 1, st ^ 1); CP_WAIT1(); }
        else             { CP_WAIT0(); }
        __syncthreads();

        uint32_t sA  = sbase + st * STAGE_B;
        uint32_t sAl = sA + HALF_B;
        uint32_t sB  = sA + 2 * HALF_B;
        uint32_t sBl = sA + 3 * HALF_B;

        #pragma unroll
        for (int sub = 0; sub < 2; sub++) {
            uint32_t ko = (uint32_t)(sub * 32);
            uint32_t ahi[2][4], alo[2][4];
            #pragma unroll
            for (int mi = 0; mi < 2; mi++) {
                uint32_t ao_ = (uint32_t)(wm * 32 + mi * 16 + l15) * 80 + ko + lhi * 16;
                ldsm4(sA + ao_,  ahi[mi][0], ahi[mi][1], ahi[mi][2], ahi[mi][3]);
                ldsm4(sAl + ao_, alo[mi][0], alo[mi][1], alo[mi][2], alo[mi][3]);
            }
            #pragma unroll
            for (int p = 0; p < 4; p++) {
                uint32_t bo_ = (uint32_t)(wn * 64 + p * 16 + (g8 >> 1) * 8 + l7) * 80
                             + ko + (g8 & 1) * 16;
                uint32_t bh[4], bl[4];
                ldsm4(sB + bo_,  bh[0], bh[1], bh[2], bh[3]);
                ldsm4(sBl + bo_, bl[0], bl[1], bl[2], bl[3]);
                #pragma unroll
                for (int mi = 0; mi < 2; mi++) {
                    MMA_BF16(acc[mi][2 * p],     ahi[mi], bh[0], bh[1]);
                    MMA_BF16(acc[mi][2 * p],     ahi[mi], bl[0], bl[1]);
                    MMA_BF16(acc[mi][2 * p],     alo[mi], bh[0], bh[1]);
                    MMA_BF16(acc[mi][2 * p + 1], ahi[mi], bh[2], bh[3]);
                    MMA_BF16(acc[mi][2 * p + 1], ahi[mi], bl[2], bl[3]);
                    MMA_BF16(acc[mi][2 * p + 1], alo[mi], bh[2], bh[3]);
                }
            }
        }
        __syncthreads();
    }

    int colp = kq * 2;
    if (mode == 0) {
        #pragma unroll
        for (int ni = 0; ni < 8; ni++) {
            int rf = bx * 128 + wn * 64 + ni * 8 + colp;
            int t = rf / C_;
            int rem = rf - t * C_;
            int h = rem >> 6, d = rem & 63;
            #pragma unroll
            for (int mi = 0; mi < 2; mi++) {
                int mb = by * 128 + wm * 32 + mi * 16 + rq;
                #pragma unroll
                for (int rr = 0; rr < 2; rr++) {
                    int m = mb + rr * 8;
                    int n = m >> 10, s = m & 1023;
                    int nh = n * NH_ + h;
                    float v0 = acc[mi][ni][rr * 2], v1 = acc[mi][ni][rr * 2 + 1];
                    if (t == 0) {
                        *(uint32_t*)(g_qh + ((size_t)nh * S_ + s) * D_ + d) =
                            hpair(v0 * 0.125f, v1 * 0.125f);
                    } else if (t == 1) {
                        *(uint32_t*)(g_kh + ((size_t)nh * S_ + s) * D_ + d) =
                            hpair(v0, v1);
                    } else {
                        size_t o0 = ((size_t)nh * D_ + d) * S_ + s;
                        g_v[o0]      = __float2half(v0);
                        g_v[o0 + S_] = __float2half(v1);
                    }
                }
            }
        }
    } else {
        #pragma unroll
        for (int ni = 0; ni < 8; ni++) {
            int m = bx * 128 + wn * 64 + ni * 8 + colp;
            int n = m >> 10, s = m & 1023;
            #pragma unroll
            for (int mi = 0; mi < 2; mi++) {
                int cb = by * 128 + wm * 32 + mi * 16 + rq;
                #pragma unroll
                for (int rr = 0; rr < 2; rr++) {
                    int cc = cb + rr * 8;
                    float bb = bias[cc];
                    float2 v = make_float2(acc[mi][ni][rr * 2] + bb,
                                           acc[mi][ni][rr * 2 + 1] + bb);
                    *(float2*)(out + ((size_t)n * C_ + cc) * S_ + s) = v;
                }
            }
        }
    }
}

// ---------------- flash attention: fp16 1-pass QK and PV ----------------
// 256 thr; warp w owns q rows [w*16, w*16+16). 64-key tiles, 16 iters.
// Q,K,V,P all fp16; accumulators fp32. Smem 54KB -> 2 CTA/SM.
#define KVROW 144
#define KVTILE (64*KVROW)          // 9216 B
#define PB_B (128*KVROW)           // 18432 B (Q staging, then P, fp16 rows)
#define ATT2_SMEM (PB_B + 2*2*KVTILE)   // 55296

__global__ __launch_bounds__(256) void attn_mma() {
    extern __shared__ __align__(16) char smc[];
    uint32_t sb  = smem_u32(smc);
    uint32_t khS = sb + PB_B;
    uint32_t vS  = khS + 2 * KVTILE;

    int tid = threadIdx.x;
    int lane = tid & 31, w = tid >> 5;
    int rq = lane >> 2, kq = lane & 3;
    int l15 = lane & 15, lhi = lane >> 4;
    int g8 = lane >> 3, l7 = lane & 7;
    int nh = blockIdx.y, q0 = blockIdx.x * 128;

    const __half* qhg = g_qh + ((size_t)nh * S_ + q0) * D_;
    const __half* khg = g_kh + (size_t)nh * S_ * D_;
    const __half* vg  = g_v  + (size_t)nh * D_ * S_;

    // group 1: Q fp16 -> Pb region ([128 rows][144B])
    #pragma unroll
    for (int i = 0; i < 4; i++) {
        int idx = i * 256 + tid;
        int r = idx >> 3, sg = idx & 7;
        cp16(sb + (uint32_t)r * KVROW + sg * 16, qhg + (size_t)r * D_ + sg * 8);
    }
    CP_COMMIT();

    // groups 2,3: K/V tiles 0,1
    #pragma unroll
    for (int t = 0; t < 2; t++) {
        #pragma unroll
        for (int i = 0; i < 2; i++) {
            int idx = i * 256 + tid;
            int row = idx >> 3, sg = idx & 7;
            uint32_t so = (uint32_t)(t * KVTILE + row * KVROW) + sg * 16;
            cp16(khS + so, khg + (size_t)(t * 64 + row) * D_ + sg * 8);
            cp16(vS + so,  vg  + (size_t)row * S_ + t * 64 + sg * 8);
        }
        CP_COMMIT();
    }

    CP_WAIT2();
    __syncthreads();

    // Q fragments via ldmatrix (fp16)
    uint32_t qfr[4][4];
    #pragma unroll
    for (int s = 0; s < 4; s++) {
        uint32_t ao = sb + (uint32_t)(w * 16 + l15) * KVROW + s * 32 + lhi * 16;
        ldsm4(ao, qfr[s][0], qfr[s][1], qfr[s][2], qfr[s][3]);
    }
    __syncthreads();     // Pb region now reusable for P

    float o[8][4];
    #pragma unroll
    for (int n = 0; n < 8; n++)
        #pragma unroll
        for (int j = 0; j < 4; j++) o[n][j] = 0.0f;
    float m0 = -1e30f, m1 = -1e30f, l0 = 0.0f, l1 = 0.0f;

    // per-thread P row bases (fp16 rows of 144B)
    uint32_t prow0 = sb + (uint32_t)(w * 16 + rq) * KVROW;
    uint32_t prow1 = prow0 + 8 * KVROW;

    for (int kt = 0; kt < 16; kt++) {
        if (kt < 15) { CP_WAIT1(); } else { CP_WAIT0(); }
        __syncthreads();
        uint32_t boff = (uint32_t)((kt & 1) * KVTILE);

        // ---- QK^T: single-pass fp16 ----
        float acc[8][4];
        #pragma unroll
        for (int n = 0; n < 8; n++)
            #pragma unroll
            for (int j = 0; j < 4; j++) acc[n][j] = 0.0f;

        #pragma unroll
        for (int s = 0; s < 4; s++) {
            #pragma unroll
            for (int p = 0; p < 4; p++) {
                uint32_t bo = boff + (uint32_t)(p * 16 + (g8 >> 1) * 8 + l7) * KVROW
                            + s * 32 + (g8 & 1) * 16;
                uint32_t b0, b1, b2, b3;
                ldsm4(khS + bo, b0, b1, b2, b3);
                MMA_F16(acc[2 * p],     qfr[s], b0, b1);
                MMA_F16(acc[2 * p + 1], qfr[s], b2, b3);
            }
        }

        // ---- softmax ----
        float t0 = -1e30f, t1 = -1e30f;
        #pragma unroll
        for (int n = 0; n < 8; n++) {
            t0 = fmaxf(t0, fmaxf(acc[n][0], acc[n][1]));
            t1 = fmaxf(t1, fmaxf(acc[n][2], acc[n][3]));
        }
        t0 = fmaxf(t0, __shfl_xor_sync(0xffffffffu, t0, 1));
        t0 = fmaxf(t0, __shfl_xor_sync(0xffffffffu, t0, 2));
        t1 = fmaxf(t1, __shfl_xor_sync(0xffffffffu, t1, 1));
        t1 = fmaxf(t1, __shfl_xor_sync(0xffffffffu, t1, 2));
        float mn0 = fmaxf(m0, t0), mn1 = fmaxf(m1, t1);
        float c0 = __expf(m0 - mn0), c1 = __expf(m1 - mn1);
        m0 = mn0; m1 = mn1;
        l0 *= c0; l1 *= c1;
        #pragma unroll
        for (int n = 0; n < 8; n++) {
            o[n][0] *= c0; o[n][1] *= c0; o[n][2] *= c1; o[n][3] *= c1;
        }

        // ---- P -> smem fp16 ----
        #pragma unroll
        for (int n = 0; n < 8; n++) {
            float p0 = __expf(acc[n][0] - m0), p1 = __expf(acc[n][1] - m0);
            float p2 = __expf(acc[n][2] - m1), p3 = __expf(acc[n][3] - m1);
            l0 += p0 + p1; l1 += p2 + p3;
            sts32(prow0 + kq * 4 + n * 16, hpair(p0, p1));
            sts32(prow1 + kq * 4 + n * 16, hpair(p2, p3));
        }
        __syncwarp();

        // ---- PV: single-pass fp16 ----
        #pragma unroll
        for (int t4 = 0; t4 < 4; t4++) {
            uint32_t po = (uint32_t)(t4 * 32 + kq * 4);
            uint32_t pf[4];
            pf[0] = lds32(prow0 + po);
            pf[1] = lds32(prow1 + po);
            pf[2] = lds32(prow0 + po + 16);
            pf[3] = lds32(prow1 + po + 16);
            #pragma unroll
            for (int p = 0; p < 4; p++) {
                uint32_t bo = boff + (uint32_t)(p * 16 + (g8 >> 1) * 8 + l7) * KVROW
                            + t4 * 32 + (g8 & 1) * 16;
                uint32_t b0, b1, b2, b3;
                ldsm4(vS + bo, b0, b1, b2, b3);
                MMA_F16(o[2 * p],     pf, b0, b1);
                MMA_F16(o[2 * p + 1], pf, b2, b3);
            }
        }
        __syncthreads();

        if (kt + 2 < 16) {
            int t = kt + 2;
            #pragma unroll
            for (int i = 0; i < 2; i++) {
                int idx = i * 256 + tid;
                int row = idx >> 3, sg = idx & 7;
                uint32_t so = boff + (uint32_t)(row * KVROW) + sg * 16;
                cp16(khS + so, khg + (size_t)(t * 64 + row) * D_ + sg * 8);
                cp16(vS + so,  vg  + (size_t)row * S_ + t * 64 + sg * 8);
            }
            CP_COMMIT();
        }
    }

    // ---- epilogue: normalize + bf16 hi/lo split -> g_ao_hi/lo ----
    l0 += __shfl_xor_sync(0xffffffffu, l0, 1);
    l0 += __shfl_xor_sync(0xffffffffu, l0, 2);
    l1 += __shfl_xor_sync(0xffffffffu, l1, 1);
    l1 += __shfl_xor_sync(0xffffffffu, l1, 2);
    float i0 = 1.0f / l0, i1 = 1.0f / l1;
    int nb = nh / NH_, hh = nh % NH_;
    int r0g = q0 + w * 16 + rq;
    size_t m0r = (size_t)(nb * S_ + r0g) * C_ + hh * 64 + kq * 2;
    size_t m1r = m0r + (size_t)8 * C_;
    #pragma unroll
    for (int n = 0; n < 8; n++) {
        float a0 = o[n][0] * i0, a1 = o[n][1] * i0;
        float b0 = o[n][2] * i1, b1 = o[n][3] * i1;
        uint32_t h, l;
        bfsplit2(a0, a1, h, l);
        *(uint32_t*)(g_ao_hi + m0r + n * 8) = h;
        *(uint32_t*)(g_ao_lo + m0r + n * 8) = l;
        bfsplit2(b0, b1, h, l);
        *(uint32_t*)(g_ao_hi + m1r + n * 8) = h;
        *(uint32_t*)(g_ao_lo + m1r + n * 8) = l;
    }
}

// ---------------- launch ----------------
extern "C" void kernel_launch(void* const* d_in, const int* in_sizes, int n_in,
                              void* d_out, int out_size) {
    const float* x     = (const float*)d_in[0];
    const float* w_qkv = (const float*)d_in[1];
    const float* w_out = (const float*)d_in[2];
    const float* b_out = (const float*)d_in[3];
    float* out = (float*)d_out;

    cudaFuncSetAttribute(mma_gemm, cudaFuncAttributeMaxDynamicSharedMemorySize, GEMM_SMEM);
    cudaFuncSetAttribute(attn_mma, cudaFuncAttributeMaxDynamicSharedMemorySize, ATT2_SMEM);

    transpose_x<<<dim3(S_ / 32, C_ / 32, N_), dim3(32, 8)>>>(x);
    split_wqkv<<<(C3_ * C_ + 255) / 256, 256>>>(w_qkv);
    split_wout<<<(C_ * C_ + 255) / 256, 256>>>(w_out);

    mma_gemm<<<dim3(C3_ / 128, M_ / 128), 256, GEMM_SMEM>>>(0, nullptr, nullptr);

    attn_mma<<<dim3(S_ / 128, N_ * NH_), 256, ATT2_SMEM>>>();

    mma_gemm<<<dim3(M_ / 128, C_ / 128), 256, GEMM_SMEM>>>(1, b_out, out);
}

// round 15
// speedup vs baseline: 1.9065x; 1.2196x over previous
#include <cuda_runtime.h>
#include <cuda_bf16.h>
#include <cuda_fp16.h>
#include <cstdint>

#define N_   16
#define C_   384
#define S_   1024
#define NH_  6
#define D_   64
#define C3_  1152
#define M_   (N_*S_)

__device__ __half g_tok_hi[M_*C_],  g_tok_lo[M_*C_];   // tokens fp16 hi/lo (exact split)
__device__ __half g_wqkv[C3_*C_];                      // w_qkv fp16 (rounded)
__device__ __half g_wout_hi[C_*C_], g_wout_lo[C_*C_];  // w_out fp16 hi/lo (exact split)
__device__ __half g_qh[N_*NH_*S_*D_];                  // fp16, 0.125 folded
__device__ __half g_kh[N_*NH_*S_*D_];                  // fp16
__device__ __half g_v[N_*NH_*D_*S_];                   // V^T fp16 [nh][d][s]
__device__ __half g_ao[M_*C_];                         // attention out fp16

__device__ __forceinline__ uint32_t smem_u32(const void* p) {
    uint32_t a;
    asm("{ .reg .u64 t; cvta.to.shared.u64 t, %1; cvt.u32.u64 %0, t; }" : "=r"(a) : "l"(p));
    return a;
}
__device__ __forceinline__ uint32_t lds32(uint32_t a) {
    uint32_t v; asm volatile("ld.shared.b32 %0, [%1];" : "=r"(v) : "r"(a)); return v;
}
__device__ __forceinline__ void sts32(uint32_t a, uint32_t v) {
    asm volatile("st.shared.b32 [%0], %1;" :: "r"(a), "r"(v) : "memory");
}
__device__ __forceinline__ void ldsm4(uint32_t a, uint32_t& r0, uint32_t& r1,
                                      uint32_t& r2, uint32_t& r3) {
    asm volatile("ldmatrix.sync.aligned.m8n8.x4.shared.b16 {%0,%1,%2,%3}, [%4];"
        : "=r"(r0), "=r"(r1), "=r"(r2), "=r"(r3) : "r"(a));
}
__device__ __forceinline__ void cp16(uint32_t saddr, const void* g) {
    size_t ga = __cvta_generic_to_global(g);
    asm volatile("cp.async.cg.shared.global [%0], [%1], 16;" :: "r"(saddr), "l"(ga) : "memory");
}
#define CP_COMMIT() asm volatile("cp.async.commit_group;" ::: "memory")
#define CP_WAIT0()  asm volatile("cp.async.wait_group 0;" ::: "memory")
#define CP_WAIT1()  asm volatile("cp.async.wait_group 1;" ::: "memory")
#define CP_WAIT2()  asm volatile("cp.async.wait_group 2;" ::: "memory")

__device__ __forceinline__ uint32_t hpair(float a, float b) {
    __half2 t = __floats2half2_rn(a, b);
    return *(uint32_t*)&t;
}

#define MMA_F16(d, a, b0, b1)                                                 \
    asm volatile("mma.sync.aligned.m16n8k16.row.col.f32.f16.f16.f32 "         \
        "{%0,%1,%2,%3}, {%4,%5,%6,%7}, {%8,%9}, {%0,%1,%2,%3};"               \
        : "+f"((d)[0]), "+f"((d)[1]), "+f"((d)[2]), "+f"((d)[3])              \
        : "r"((a)[0]), "r"((a)[1]), "r"((a)[2]), "r"((a)[3]),                 \
          "r"(b0), "r"(b1))

// ---------------- input prep ----------------
__global__ void transpose_x(const float* __restrict__ x) {
    __shared__ float t[32][33];
    int n = blockIdx.z, k0 = blockIdx.y * 32, s0 = blockIdx.x * 32;
    int tx = threadIdx.x, ty = threadIdx.y;
    const float* src = x + ((size_t)n * C_ + k0) * S_ + s0;
    #pragma unroll
    for (int j = 0; j < 4; j++)
        t[ty + 8 * j][tx] = src[(size_t)(ty + 8 * j) * S_ + tx];
    __syncthreads();
    size_t base = ((size_t)n * S_ + s0) * C_ + k0;
    #pragma unroll
    for (int j = 0; j < 4; j++) {
        float a = t[tx][ty + 8 * j];
        __half h = __float2half(a);
        size_t o = base + (size_t)(ty + 8 * j) * C_ + tx;
        g_tok_hi[o] = h;
        g_tok_lo[o] = __float2half(a - __half2float(h));
    }
}
__global__ void split_wqkv(const float* __restrict__ w) {
    int i = blockIdx.x * 256 + threadIdx.x;
    if (i < C3_ * C_) g_wqkv[i] = __float2half(w[i]);
}
__global__ void split_wout(const float* __restrict__ w) {
    int i = blockIdx.x * 256 + threadIdx.x;
    if (i < C_ * C_) {
        float a = w[i]; __half h = __float2half(a);
        g_wout_hi[i] = h; g_wout_lo[i] = __float2half(a - __half2float(h));
    }
}

// ---------------- 2-pass fp16 mma.sync GEMM (A split hi/lo, B rounded) -----
// mode 0: D[m][r] = tok[m][k].wqkv[r][k]   grid(9,128)  -> q/k/v scatter
// mode 1: D[c][m] = wout[c][k].ao[m][k]    grid(128,3)  -> out[n][c][s]+bias
#define KCH 32
#define HALF_B (128*80)            // one array: 128 rows x 80B
#define STAGE_B (3*HALF_B)         // Ah + Al + B
#define GEMM_SMEM (2*STAGE_B)      // 61440

__global__ __launch_bounds__(256) void mma_gemm(
    int mode, const float* __restrict__ bias, float* __restrict__ out)
{
    extern __shared__ __align__(16) char smem[];
    uint32_t sbase = smem_u32(smem);
    int tid = threadIdx.x;
    int lane = tid & 31, w = tid >> 5;
    int wm = w & 3, wn = w >> 2;
    int by = blockIdx.y, bx = blockIdx.x;
    int rq = lane >> 2, kq = lane & 3;
    int l15 = lane & 15, lhi = lane >> 4;
    int g8 = lane >> 3, l7 = lane & 7;

    const __half *Ahp, *Alp, *Bp;
    if (mode == 0) { Ahp = g_tok_hi;  Alp = g_tok_lo;  Bp = g_wqkv; }
    else           { Ahp = g_wout_hi; Alp = g_wout_lo; Bp = g_ao; }
    const __half* Ah = Ahp + (size_t)by * 128 * C_;
    const __half* Al = Alp + (size_t)by * 128 * C_;
    const __half* Bb = Bp  + (size_t)bx * 128 * C_;

    float acc[2][8][4];
    #pragma unroll
    for (int i = 0; i < 2; i++)
        #pragma unroll
        for (int j = 0; j < 8; j++)
            #pragma unroll
            for (int q = 0; q < 4; q++) acc[i][j][q] = 0.0f;

    auto issue = [&](int c, int st) {
        uint32_t s0 = sbase + st * STAGE_B;
        #pragma unroll
        for (int i = 0; i < 2; i++) {
            int idx = i * 256 + tid;
            int row = idx >> 2, seg = idx & 3;
            size_t go = (size_t)row * C_ + c * KCH + seg * 8;
            uint32_t so = row * 80 + seg * 16;
            cp16(s0 + so,              Ah + go);
            cp16(s0 + HALF_B + so,     Al + go);
            cp16(s0 + 2 * HALF_B + so, Bb + go);
        }
        CP_COMMIT();
    };

    const int NCH = C_ / KCH;   // 12
    issue(0, 0);
    for (int c = 0; c < NCH; c++) {
        int st = c & 1;
        if (c + 1 < NCH) { issue(c + 1, st ^ 1); CP_WAIT1(); }
        else             { CP_WAIT0(); }
        __syncthreads();

        uint32_t sA  = sbase + st * STAGE_B;
        uint32_t sAl = sA + HALF_B;
        uint32_t sB  = sA + 2 * HALF_B;

        #pragma unroll
        for (int sub = 0; sub < 2; sub++) {
            uint32_t ko = (uint32_t)(sub * 32);
            uint32_t ahi[2][4], alo[2][4];
            #pragma unroll
            for (int mi = 0; mi < 2; mi++) {
                uint32_t ao_ = (uint32_t)(wm * 32 + mi * 16 + l15) * 80 + ko + lhi * 16;
                ldsm4(sA + ao_,  ahi[mi][0], ahi[mi][1], ahi[mi][2], ahi[mi][3]);
                ldsm4(sAl + ao_, alo[mi][0], alo[mi][1], alo[mi][2], alo[mi][3]);
            }
            #pragma unroll
            for (int p = 0; p < 4; p++) {
                uint32_t bo_ = (uint32_t)(wn * 64 + p * 16 + (g8 >> 1) * 8 + l7) * 80
                             + ko + (g8 & 1) * 16;
                uint32_t bh[4];
                ldsm4(sB + bo_, bh[0], bh[1], bh[2], bh[3]);
                #pragma unroll
                for (int mi = 0; mi < 2; mi++) {
                    MMA_F16(acc[mi][2 * p],     ahi[mi], bh[0], bh[1]);
                    MMA_F16(acc[mi][2 * p],     alo[mi], bh[0], bh[1]);
                    MMA_F16(acc[mi][2 * p + 1], ahi[mi], bh[2], bh[3]);
                    MMA_F16(acc[mi][2 * p + 1], alo[mi], bh[2], bh[3]);
                }
            }
        }
        __syncthreads();
    }

    int colp = kq * 2;
    if (mode == 0) {
        #pragma unroll
        for (int ni = 0; ni < 8; ni++) {
            int rf = bx * 128 + wn * 64 + ni * 8 + colp;
            int t = rf / C_;
            int rem = rf - t * C_;
            int h = rem >> 6, d = rem & 63;
            #pragma unroll
            for (int mi = 0; mi < 2; mi++) {
                int mb = by * 128 + wm * 32 + mi * 16 + rq;
                #pragma unroll
                for (int rr = 0; rr < 2; rr++) {
                    int m = mb + rr * 8;
                    int n = m >> 10, s = m & 1023;
                    int nh = n * NH_ + h;
                    float v0 = acc[mi][ni][rr * 2], v1 = acc[mi][ni][rr * 2 + 1];
                    if (t == 0) {
                        *(uint32_t*)(g_qh + ((size_t)nh * S_ + s) * D_ + d) =
                            hpair(v0 * 0.125f, v1 * 0.125f);
                    } else if (t == 1) {
                        *(uint32_t*)(g_kh + ((size_t)nh * S_ + s) * D_ + d) =
                            hpair(v0, v1);
                    } else {
                        size_t o0 = ((size_t)nh * D_ + d) * S_ + s;
                        g_v[o0]      = __float2half(v0);
                        g_v[o0 + S_] = __float2half(v1);
                    }
                }
            }
        }
    } else {
        #pragma unroll
        for (int ni = 0; ni < 8; ni++) {
            int m = bx * 128 + wn * 64 + ni * 8 + colp;
            int n = m >> 10, s = m & 1023;
            #pragma unroll
            for (int mi = 0; mi < 2; mi++) {
                int cb = by * 128 + wm * 32 + mi * 16 + rq;
                #pragma unroll
                for (int rr = 0; rr < 2; rr++) {
                    int cc = cb + rr * 8;
                    float bb = bias[cc];
                    float2 v = make_float2(acc[mi][ni][rr * 2] + bb,
                                           acc[mi][ni][rr * 2 + 1] + bb);
                    *(float2*)(out + ((size_t)n * C_ + cc) * S_ + s) = v;
                }
            }
        }
    }
}

// ---------------- flash attention: fp16 1-pass QK and PV (round-14) --------
#define KVROW 144
#define KVTILE (64*KVROW)
#define PB_B (128*KVROW)
#define ATT2_SMEM (PB_B + 2*2*KVTILE)   // 55296

__global__ __launch_bounds__(256) void attn_mma() {
    extern __shared__ __align__(16) char smc[];
    uint32_t sb  = smem_u32(smc);
    uint32_t khS = sb + PB_B;
    uint32_t vS  = khS + 2 * KVTILE;

    int tid = threadIdx.x;
    int lane = tid & 31, w = tid >> 5;
    int rq = lane >> 2, kq = lane & 3;
    int l15 = lane & 15, lhi = lane >> 4;
    int g8 = lane >> 3, l7 = lane & 7;
    int nh = blockIdx.y, q0 = blockIdx.x * 128;

    const __half* qhg = g_qh + ((size_t)nh * S_ + q0) * D_;
    const __half* khg = g_kh + (size_t)nh * S_ * D_;
    const __half* vg  = g_v  + (size_t)nh * D_ * S_;

    #pragma unroll
    for (int i = 0; i < 4; i++) {
        int idx = i * 256 + tid;
        int r = idx >> 3, sg = idx & 7;
        cp16(sb + (uint32_t)r * KVROW + sg * 16, qhg + (size_t)r * D_ + sg * 8);
    }
    CP_COMMIT();

    #pragma unroll
    for (int t = 0; t < 2; t++) {
        #pragma unroll
        for (int i = 0; i < 2; i++) {
            int idx = i * 256 + tid;
            int row = idx >> 3, sg = idx & 7;
            uint32_t so = (uint32_t)(t * KVTILE + row * KVROW) + sg * 16;
            cp16(khS + so, khg + (size_t)(t * 64 + row) * D_ + sg * 8);
            cp16(vS + so,  vg  + (size_t)row * S_ + t * 64 + sg * 8);
        }
        CP_COMMIT();
    }

    CP_WAIT2();
    __syncthreads();

    uint32_t qfr[4][4];
    #pragma unroll
    for (int s = 0; s < 4; s++) {
        uint32_t ao = sb + (uint32_t)(w * 16 + l15) * KVROW + s * 32 + lhi * 16;
        ldsm4(ao, qfr[s][0], qfr[s][1], qfr[s][2], qfr[s][3]);
    }
    __syncthreads();

    float o[8][4];
    #pragma unroll
    for (int n = 0; n < 8; n++)
        #pragma unroll
        for (int j = 0; j < 4; j++) o[n][j] = 0.0f;
    float m0 = -1e30f, m1 = -1e30f, l0 = 0.0f, l1 = 0.0f;

    uint32_t prow0 = sb + (uint32_t)(w * 16 + rq) * KVROW;
    uint32_t prow1 = prow0 + 8 * KVROW;

    for (int kt = 0; kt < 16; kt++) {
        if (kt < 15) { CP_WAIT1(); } else { CP_WAIT0(); }
        __syncthreads();
        uint32_t boff = (uint32_t)((kt & 1) * KVTILE);

        float acc[8][4];
        #pragma unroll
        for (int n = 0; n < 8; n++)
            #pragma unroll
            for (int j = 0; j < 4; j++) acc[n][j] = 0.0f;

        #pragma unroll
        for (int s = 0; s < 4; s++) {
            #pragma unroll
            for (int p = 0; p < 4; p++) {
                uint32_t bo = boff + (uint32_t)(p * 16 + (g8 >> 1) * 8 + l7) * KVROW
                            + s * 32 + (g8 & 1) * 16;
                uint32_t b0, b1, b2, b3;
                ldsm4(khS + bo, b0, b1, b2, b3);
                MMA_F16(acc[2 * p],     qfr[s], b0, b1);
                MMA_F16(acc[2 * p + 1], qfr[s], b2, b3);
            }
        }

        float t0 = -1e30f, t1 = -1e30f;
        #pragma unroll
        for (int n = 0; n < 8; n++) {
            t0 = fmaxf(t0, fmaxf(acc[n][0], acc[n][1]));
            t1 = fmaxf(t1, fmaxf(acc[n][2], acc[n][3]));
        }
        t0 = fmaxf(t0, __shfl_xor_sync(0xffffffffu, t0, 1));
        t0 = fmaxf(t0, __shfl_xor_sync(0xffffffffu, t0, 2));
        t1 = fmaxf(t1, __shfl_xor_sync(0xffffffffu, t1, 1));
        t1 = fmaxf(t1, __shfl_xor_sync(0xffffffffu, t1, 2));
        float mn0 = fmaxf(m0, t0), mn1 = fmaxf(m1, t1);
        float c0 = __expf(m0 - mn0), c1 = __expf(m1 - mn1);
        m0 = mn0; m1 = mn1;
        l0 *= c0; l1 *= c1;
        #pragma unroll
        for (int n = 0; n < 8; n++) {
            o[n][0] *= c0; o[n][1] *= c0; o[n][2] *= c1; o[n][3] *= c1;
        }

        #pragma unroll
        for (int n = 0; n < 8; n++) {
            float p0 = __expf(acc[n][0] - m0), p1 = __expf(acc[n][1] - m0);
            float p2 = __expf(acc[n][2] - m1), p3 = __expf(acc[n][3] - m1);
            l0 += p0 + p1; l1 += p2 + p3;
            sts32(prow0 + kq * 4 + n * 16, hpair(p0, p1));
            sts32(prow1 + kq * 4 + n * 16, hpair(p2, p3));
        }
        __syncwarp();

        #pragma unroll
        for (int t4 = 0; t4 < 4; t4++) {
            uint32_t po = (uint32_t)(t4 * 32 + kq * 4);
            uint32_t pf[4];
            pf[0] = lds32(prow0 + po);
            pf[1] = lds32(prow1 + po);
            pf[2] = lds32(prow0 + po + 16);
            pf[3] = lds32(prow1 + po + 16);
            #pragma unroll
            for (int p = 0; p < 4; p++) {
                uint32_t bo = boff + (uint32_t)(p * 16 + (g8 >> 1) * 8 + l7) * KVROW
                            + t4 * 32 + (g8 & 1) * 16;
                uint32_t b0, b1, b2, b3;
                ldsm4(vS + bo, b0, b1, b2, b3);
                MMA_F16(o[2 * p],     pf, b0, b1);
                MMA_F16(o[2 * p + 1], pf, b2, b3);
            }
        }
        __syncthreads();

        if (kt + 2 < 16) {
            int t = kt + 2;
            #pragma unroll
            for (int i = 0; i < 2; i++) {
                int idx = i * 256 + tid;
                int row = idx >> 3, sg = idx & 7;
                uint32_t so = boff + (uint32_t)(row * KVROW) + sg * 16;
                cp16(khS + so, khg + (size_t)(t * 64 + row) * D_ + sg * 8);
                cp16(vS + so,  vg  + (size_t)row * S_ + t * 64 + sg * 8);
            }
            CP_COMMIT();
        }
    }

    // ---- epilogue: normalize -> g_ao fp16 ----
    l0 += __shfl_xor_sync(0xffffffffu, l0, 1);
    l0 += __shfl_xor_sync(0xffffffffu, l0, 2);
    l1 += __shfl_xor_sync(0xffffffffu, l1, 1);
    l1 += __shfl_xor_sync(0xffffffffu, l1, 2);
    float i0 = 1.0f / l0, i1 = 1.0f / l1;
    int nb = nh / NH_, hh = nh % NH_;
    int r0g = q0 + w * 16 + rq;
    size_t m0r = (size_t)(nb * S_ + r0g) * C_ + hh * 64 + kq * 2;
    size_t m1r = m0r + (size_t)8 * C_;
    #pragma unroll
    for (int n = 0; n < 8; n++) {
        *(uint32_t*)(g_ao + m0r + n * 8) = hpair(o[n][0] * i0, o[n][1] * i0);
        *(uint32_t*)(g_ao + m1r + n * 8) = hpair(o[n][2] * i1, o[n][3] * i1);
    }
}

// ---------------- launch ----------------
extern "C" void kernel_launch(void* const* d_in, const int* in_sizes, int n_in,
                              void* d_out, int out_size) {
    const float* x     = (const float*)d_in[0];
    const float* w_qkv = (const float*)d_in[1];
    const float* w_out = (const float*)d_in[2];
    const float* b_out = (const float*)d_in[3];
    float* out = (float*)d_out;

    cudaFuncSetAttribute(mma_gemm, cudaFuncAttributeMaxDynamicSharedMemorySize, GEMM_SMEM);
    cudaFuncSetAttribute(attn_mma, cudaFuncAttributeMaxDynamicSharedMemorySize, ATT2_SMEM);

    transpose_x<<<dim3(S_ / 32, C_ / 32, N_), dim3(32, 8)>>>(x);
    split_wqkv<<<(C3_ * C_ + 255) / 256, 256>>>(w_qkv);
    split_wout<<<(C_ * C_ + 255) / 256, 256>>>(w_out);

    mma_gemm<<<dim3(C3_ / 128, M_ / 128), 256, GEMM_SMEM>>>(0, nullptr, nullptr);

    attn_mma<<<dim3(S_ / 128, N_ * NH_), 256, ATT2_SMEM>>>();

    mma_gemm<<<dim3(M_ / 128, C_ / 128), 256, GEMM_SMEM>>>(1, b_out, out);
}

// round 16
// speedup vs baseline: 2.2980x; 1.2053x over previous
#include <cuda_runtime.h>
#include <cuda_fp16.h>
#include <cstdint>

#define N_   16
#define C_   384
#define S_   1024
#define NH_  6
#define D_   64
#define C3_  1152
#define M_   (N_*S_)

__device__ __half g_tok[M_*C_];                        // tokens fp16 [m][k]
__device__ __half g_wqkv[C3_*C_];                      // w_qkv fp16 [r][k]
__device__ __half g_wout[C_*C_];                       // w_out fp16 [c][k]
__device__ __half g_qh[N_*NH_*S_*D_];                  // fp16, 0.125 folded
__device__ __half g_kh[N_*NH_*S_*D_];                  // fp16
__device__ __half g_v[N_*NH_*D_*S_];                   // V^T fp16 [nh][d][s]
__device__ __half g_ao[M_*C_];                         // attention out fp16

__device__ __forceinline__ uint32_t smem_u32(const void* p) {
    uint32_t a;
    asm("{ .reg .u64 t; cvta.to.shared.u64 t, %1; cvt.u32.u64 %0, t; }" : "=r"(a) : "l"(p));
    return a;
}
__device__ __forceinline__ uint32_t lds32(uint32_t a) {
    uint32_t v; asm volatile("ld.shared.b32 %0, [%1];" : "=r"(v) : "r"(a)); return v;
}
__device__ __forceinline__ void sts32(uint32_t a, uint32_t v) {
    asm volatile("st.shared.b32 [%0], %1;" :: "r"(a), "r"(v) : "memory");
}
__device__ __forceinline__ void ldsm4(uint32_t a, uint32_t& r0, uint32_t& r1,
                                      uint32_t& r2, uint32_t& r3) {
    asm volatile("ldmatrix.sync.aligned.m8n8.x4.shared.b16 {%0,%1,%2,%3}, [%4];"
        : "=r"(r0), "=r"(r1), "=r"(r2), "=r"(r3) : "r"(a));
}
__device__ __forceinline__ void cp16(uint32_t saddr, const void* g) {
    size_t ga = __cvta_generic_to_global(g);
    asm volatile("cp.async.cg.shared.global [%0], [%1], 16;" :: "r"(saddr), "l"(ga) : "memory");
}
#define CP_COMMIT() asm volatile("cp.async.commit_group;" ::: "memory")
#define CP_WAIT0()  asm volatile("cp.async.wait_group 0;" ::: "memory")
#define CP_WAIT1()  asm volatile("cp.async.wait_group 1;" ::: "memory")
#define CP_WAIT2()  asm volatile("cp.async.wait_group 2;" ::: "memory")

__device__ __forceinline__ uint32_t hpair(float a, float b) {
    __half2 t = __floats2half2_rn(a, b);
    return *(uint32_t*)&t;
}

#define MMA_F16(d, a, b0, b1)                                                 \
    asm volatile("mma.sync.aligned.m16n8k16.row.col.f32.f16.f16.f32 "         \
        "{%0,%1,%2,%3}, {%4,%5,%6,%7}, {%8,%9}, {%0,%1,%2,%3};"               \
        : "+f"((d)[0]), "+f"((d)[1]), "+f"((d)[2]), "+f"((d)[3])              \
        : "r"((a)[0]), "r"((a)[1]), "r"((a)[2]), "r"((a)[3]),                 \
          "r"(b0), "r"(b1))

// ---------------- input prep ----------------
__global__ void transpose_x(const float* __restrict__ x) {
    __shared__ float t[32][33];
    int n = blockIdx.z, k0 = blockIdx.y * 32, s0 = blockIdx.x * 32;
    int tx = threadIdx.x, ty = threadIdx.y;
    const float* src = x + ((size_t)n * C_ + k0) * S_ + s0;
    #pragma unroll
    for (int j = 0; j < 4; j++)
        t[ty + 8 * j][tx] = src[(size_t)(ty + 8 * j) * S_ + tx];
    __syncthreads();
    size_t base = ((size_t)n * S_ + s0) * C_ + k0;
    #pragma unroll
    for (int j = 0; j < 4; j++)
        g_tok[base + (size_t)(ty + 8 * j) * C_ + tx] = __float2half(t[tx][ty + 8 * j]);
}
__global__ void split_wqkv(const float* __restrict__ w) {
    int i = blockIdx.x * 256 + threadIdx.x;
    if (i < C3_ * C_) g_wqkv[i] = __float2half(w[i]);
}
__global__ void split_wout(const float* __restrict__ w) {
    int i = blockIdx.x * 256 + threadIdx.x;
    if (i < C_ * C_) g_wout[i] = __float2half(w[i]);
}

// ---------------- 1-pass fp16 mma.sync GEMM ----------------
// mode 0: D[m][r] = tok[m][k].wqkv[r][k]   grid(9,128)  -> q/k/v scatter
// mode 1: D[c][m] = wout[c][k].ao[m][k]    grid(128,3)  -> out[n][c][s]+bias
#define KCH 32
#define HALF_B (128*80)            // one array: 128 rows x 80B
#define STAGE_B (2*HALF_B)         // A + B
#define GEMM_SMEM (2*STAGE_B)      // 40960

__global__ __launch_bounds__(256) void mma_gemm(
    int mode, const float* __restrict__ bias, float* __restrict__ out)
{
    extern __shared__ __align__(16) char smem[];
    uint32_t sbase = smem_u32(smem);
    int tid = threadIdx.x;
    int lane = tid & 31, w = tid >> 5;
    int wm = w & 3, wn = w >> 2;
    int by = blockIdx.y, bx = blockIdx.x;
    int rq = lane >> 2, kq = lane & 3;
    int l15 = lane & 15, lhi = lane >> 4;
    int g8 = lane >> 3, l7 = lane & 7;

    const __half *Ap, *Bp;
    if (mode == 0) { Ap = g_tok;  Bp = g_wqkv; }
    else           { Ap = g_wout; Bp = g_ao; }
    const __half* Ab = Ap + (size_t)by * 128 * C_;
    const __half* Bb = Bp + (size_t)bx * 128 * C_;

    float acc[2][8][4];
    #pragma unroll
    for (int i = 0; i < 2; i++)
        #pragma unroll
        for (int j = 0; j < 8; j++)
            #pragma unroll
            for (int q = 0; q < 4; q++) acc[i][j][q] = 0.0f;

    auto issue = [&](int c, int st) {
        uint32_t s0 = sbase + st * STAGE_B;
        #pragma unroll
        for (int i = 0; i < 2; i++) {
            int idx = i * 256 + tid;
            int row = idx >> 2, seg = idx & 3;
            size_t go = (size_t)row * C_ + c * KCH + seg * 8;
            uint32_t so = row * 80 + seg * 16;
            cp16(s0 + so,          Ab + go);
            cp16(s0 + HALF_B + so, Bb + go);
        }
        CP_COMMIT();
    };

    const int NCH = C_ / KCH;   // 12
    issue(0, 0);
    for (int c = 0; c < NCH; c++) {
        int st = c & 1;
        if (c + 1 < NCH) { issue(c + 1, st ^ 1); CP_WAIT1(); }
        else             { CP_WAIT0(); }
        __syncthreads();

        uint32_t sA = sbase + st * STAGE_B;
        uint32_t sB = sA + HALF_B;

        #pragma unroll
        for (int sub = 0; sub < 2; sub++) {
            uint32_t ko = (uint32_t)(sub * 32);
            uint32_t afr[2][4];
            #pragma unroll
            for (int mi = 0; mi < 2; mi++) {
                uint32_t ao_ = (uint32_t)(wm * 32 + mi * 16 + l15) * 80 + ko + lhi * 16;
                ldsm4(sA + ao_, afr[mi][0], afr[mi][1], afr[mi][2], afr[mi][3]);
            }
            #pragma unroll
            for (int p = 0; p < 4; p++) {
                uint32_t bo_ = (uint32_t)(wn * 64 + p * 16 + (g8 >> 1) * 8 + l7) * 80
                             + ko + (g8 & 1) * 16;
                uint32_t bh[4];
                ldsm4(sB + bo_, bh[0], bh[1], bh[2], bh[3]);
                #pragma unroll
                for (int mi = 0; mi < 2; mi++) {
                    MMA_F16(acc[mi][2 * p],     afr[mi], bh[0], bh[1]);
                    MMA_F16(acc[mi][2 * p + 1], afr[mi], bh[2], bh[3]);
                }
            }
        }
        __syncthreads();
    }

    int colp = kq * 2;
    if (mode == 0) {
        #pragma unroll
        for (int ni = 0; ni < 8; ni++) {
            int rf = bx * 128 + wn * 64 + ni * 8 + colp;
            int t = rf / C_;
            int rem = rf - t * C_;
            int h = rem >> 6, d = rem & 63;
            #pragma unroll
            for (int mi = 0; mi < 2; mi++) {
                int mb = by * 128 + wm * 32 + mi * 16 + rq;
                #pragma unroll
                for (int rr = 0; rr < 2; rr++) {
                    int m = mb + rr * 8;
                    int n = m >> 10, s = m & 1023;
                    int nh = n * NH_ + h;
                    float v0 = acc[mi][ni][rr * 2], v1 = acc[mi][ni][rr * 2 + 1];
                    if (t == 0) {
                        *(uint32_t*)(g_qh + ((size_t)nh * S_ + s) * D_ + d) =
                            hpair(v0 * 0.125f, v1 * 0.125f);
                    } else if (t == 1) {
                        *(uint32_t*)(g_kh + ((size_t)nh * S_ + s) * D_ + d) =
                            hpair(v0, v1);
                    } else {
                        size_t o0 = ((size_t)nh * D_ + d) * S_ + s;
                        g_v[o0]      = __float2half(v0);
                        g_v[o0 + S_] = __float2half(v1);
                    }
                }
            }
        }
    } else {
        #pragma unroll
        for (int ni = 0; ni < 8; ni++) {
            int m = bx * 128 + wn * 64 + ni * 8 + colp;
            int n = m >> 10, s = m & 1023;
            #pragma unroll
            for (int mi = 0; mi < 2; mi++) {
                int cb = by * 128 + wm * 32 + mi * 16 + rq;
                #pragma unroll
                for (int rr = 0; rr < 2; rr++) {
                    int cc = cb + rr * 8;
                    float bb = bias[cc];
                    float2 v = make_float2(acc[mi][ni][rr * 2] + bb,
                                           acc[mi][ni][rr * 2 + 1] + bb);
                    *(float2*)(out + ((size_t)n * C_ + cc) * S_ + s) = v;
                }
            }
        }
    }
}

// ---------------- flash attention: fp16 1-pass QK and PV (round-14) --------
#define KVROW 144
#define KVTILE (64*KVROW)
#define PB_B (128*KVROW)
#define ATT2_SMEM (PB_B + 2*2*KVTILE)   // 55296

__global__ __launch_bounds__(256) void attn_mma() {
    extern __shared__ __align__(16) char smc[];
    uint32_t sb  = smem_u32(smc);
    uint32_t khS = sb + PB_B;
    uint32_t vS  = khS + 2 * KVTILE;

    int tid = threadIdx.x;
    int lane = tid & 31, w = tid >> 5;
    int rq = lane >> 2, kq = lane & 3;
    int l15 = lane & 15, lhi = lane >> 4;
    int g8 = lane >> 3, l7 = lane & 7;
    int nh = blockIdx.y, q0 = blockIdx.x * 128;

    const __half* qhg = g_qh + ((size_t)nh * S_ + q0) * D_;
    const __half* khg = g_kh + (size_t)nh * S_ * D_;
    const __half* vg  = g_v  + (size_t)nh * D_ * S_;

    #pragma unroll
    for (int i = 0; i < 4; i++) {
        int idx = i * 256 + tid;
        int r = idx >> 3, sg = idx & 7;
        cp16(sb + (uint32_t)r * KVROW + sg * 16, qhg + (size_t)r * D_ + sg * 8);
    }
    CP_COMMIT();

    #pragma unroll
    for (int t = 0; t < 2; t++) {
        #pragma unroll
        for (int i = 0; i < 2; i++) {
            int idx = i * 256 + tid;
            int row = idx >> 3, sg = idx & 7;
            uint32_t so = (uint32_t)(t * KVTILE + row * KVROW) + sg * 16;
            cp16(khS + so, khg + (size_t)(t * 64 + row) * D_ + sg * 8);
            cp16(vS + so,  vg  + (size_t)row * S_ + t * 64 + sg * 8);
        }
        CP_COMMIT();
    }

    CP_WAIT2();
    __syncthreads();

    uint32_t qfr[4][4];
    #pragma unroll
    for (int s = 0; s < 4; s++) {
        uint32_t ao = sb + (uint32_t)(w * 16 + l15) * KVROW + s * 32 + lhi * 16;
        ldsm4(ao, qfr[s][0], qfr[s][1], qfr[s][2], qfr[s][3]);
    }
    __syncthreads();

    float o[8][4];
    #pragma unroll
    for (int n = 0; n < 8; n++)
        #pragma unroll
        for (int j = 0; j < 4; j++) o[n][j] = 0.0f;
    float m0 = -1e30f, m1 = -1e30f, l0 = 0.0f, l1 = 0.0f;

    uint32_t prow0 = sb + (uint32_t)(w * 16 + rq) * KVROW;
    uint32_t prow1 = prow0 + 8 * KVROW;

    for (int kt = 0; kt < 16; kt++) {
        if (kt < 15) { CP_WAIT1(); } else { CP_WAIT0(); }
        __syncthreads();
        uint32_t boff = (uint32_t)((kt & 1) * KVTILE);

        float acc[8][4];
        #pragma unroll
        for (int n = 0; n < 8; n++)
            #pragma unroll
            for (int j = 0; j < 4; j++) acc[n][j] = 0.0f;

        #pragma unroll
        for (int s = 0; s < 4; s++) {
            #pragma unroll
            for (int p = 0; p < 4; p++) {
                uint32_t bo = boff + (uint32_t)(p * 16 + (g8 >> 1) * 8 + l7) * KVROW
                            + s * 32 + (g8 & 1) * 16;
                uint32_t b0, b1, b2, b3;
                ldsm4(khS + bo, b0, b1, b2, b3);
                MMA_F16(acc[2 * p],     qfr[s], b0, b1);
                MMA_F16(acc[2 * p + 1], qfr[s], b2, b3);
            }
        }

        float t0 = -1e30f, t1 = -1e30f;
        #pragma unroll
        for (int n = 0; n < 8; n++) {
            t0 = fmaxf(t0, fmaxf(acc[n][0], acc[n][1]));
            t1 = fmaxf(t1, fmaxf(acc[n][2], acc[n][3]));
        }
        t0 = fmaxf(t0, __shfl_xor_sync(0xffffffffu, t0, 1));
        t0 = fmaxf(t0, __shfl_xor_sync(0xffffffffu, t0, 2));
        t1 = fmaxf(t1, __shfl_xor_sync(0xffffffffu, t1, 1));
        t1 = fmaxf(t1, __shfl_xor_sync(0xffffffffu, t1, 2));
        float mn0 = fmaxf(m0, t0), mn1 = fmaxf(m1, t1);
        float c0 = __expf(m0 - mn0), c1 = __expf(m1 - mn1);
        m0 = mn0; m1 = mn1;
        l0 *= c0; l1 *= c1;
        #pragma unroll
        for (int n = 0; n < 8; n++) {
            o[n][0] *= c0; o[n][1] *= c0; o[n][2] *= c1; o[n][3] *= c1;
        }

        #pragma unroll
        for (int n = 0; n < 8; n++) {
            float p0 = __expf(acc[n][0] - m0), p1 = __expf(acc[n][1] - m0);
            float p2 = __expf(acc[n][2] - m1), p3 = __expf(acc[n][3] - m1);
            l0 += p0 + p1; l1 += p2 + p3;
            sts32(prow0 + kq * 4 + n * 16, hpair(p0, p1));
            sts32(prow1 + kq * 4 + n * 16, hpair(p2, p3));
        }
        __syncwarp();

        #pragma unroll
        for (int t4 = 0; t4 < 4; t4++) {
            uint32_t po = (uint32_t)(t4 * 32 + kq * 4);
            uint32_t pf[4];
            pf[0] = lds32(prow0 + po);
            pf[1] = lds32(prow1 + po);
            pf[2] = lds32(prow0 + po + 16);
            pf[3] = lds32(prow1 + po + 16);
            #pragma unroll
            for (int p = 0; p < 4; p++) {
                uint32_t bo = boff + (uint32_t)(p * 16 + (g8 >> 1) * 8 + l7) * KVROW
                            + t4 * 32 + (g8 & 1) * 16;
                uint32_t b0, b1, b2, b3;
                ldsm4(vS + bo, b0, b1, b2, b3);
                MMA_F16(o[2 * p],     pf, b0, b1);
                MMA_F16(o[2 * p + 1], pf, b2, b3);
            }
        }
        __syncthreads();

        if (kt + 2 < 16) {
            int t = kt + 2;
            #pragma unroll
            for (int i = 0; i < 2; i++) {
                int idx = i * 256 + tid;
                int row = idx >> 3, sg = idx & 7;
                uint32_t so = boff + (uint32_t)(row * KVROW) + sg * 16;
                cp16(khS + so, khg + (size_t)(t * 64 + row) * D_ + sg * 8);
                cp16(vS + so,  vg  + (size_t)row * S_ + t * 64 + sg * 8);
            }
            CP_COMMIT();
        }
    }

    l0 += __shfl_xor_sync(0xffffffffu, l0, 1);
    l0 += __shfl_xor_sync(0xffffffffu, l0, 2);
    l1 += __shfl_xor_sync(0xffffffffu, l1, 1);
    l1 += __shfl_xor_sync(0xffffffffu, l1, 2);
    float i0 = 1.0f / l0, i1 = 1.0f / l1;
    int nb = nh / NH_, hh = nh % NH_;
    int r0g = q0 + w * 16 + rq;
    size_t m0r = (size_t)(nb * S_ + r0g) * C_ + hh * 64 + kq * 2;
    size_t m1r = m0r + (size_t)8 * C_;
    #pragma unroll
    for (int n = 0; n < 8; n++) {
        *(uint32_t*)(g_ao + m0r + n * 8) = hpair(o[n][0] * i0, o[n][1] * i0);
        *(uint32_t*)(g_ao + m1r + n * 8) = hpair(o[n][2] * i1, o[n][3] * i1);
    }
}

// ---------------- launch ----------------
extern "C" void kernel_launch(void* const* d_in, const int* in_sizes, int n_in,
                              void* d_out, int out_size) {
    const float* x     = (const float*)d_in[0];
    const float* w_qkv = (const float*)d_in[1];
    const float* w_out = (const float*)d_in[2];
    const float* b_out = (const float*)d_in[3];
    float* out = (float*)d_out;

    cudaFuncSetAttribute(mma_gemm, cudaFuncAttributeMaxDynamicSharedMemorySize, GEMM_SMEM);
    cudaFuncSetAttribute(attn_mma, cudaFuncAttributeMaxDynamicSharedMemorySize, ATT2_SMEM);

    transpose_x<<<dim3(S_ / 32, C_ / 32, N_), dim3(32, 8)>>>(x);
    split_wqkv<<<(C3_ * C_ + 255) / 256, 256>>>(w_qkv);
    split_wout<<<(C_ * C_ + 255) / 256, 256>>>(w_out);

    mma_gemm<<<dim3(C3_ / 128, M_ / 128), 256, GEMM_SMEM>>>(0, nullptr, nullptr);

    attn_mma<<<dim3(S_ / 128, N_ * NH_), 256, ATT2_SMEM>>>();

    mma_gemm<<<dim3(M_ / 128, C_ / 128), 256, GEMM_SMEM>>>(1, b_out, out);
}